// round 1
// baseline (speedup 1.0000x reference)
#include <cuda_runtime.h>
#include <cuda_bf16.h>
#include <math.h>

// Problem constants
#define BATCH   16
#define DIM     512
#define SEQL    4096
#define NFFT    1024
#define HOP     256
#define FBINS   513          // NFFT/2 + 1
#define ODIM    1026         // 2*FBINS
#define KPAD    1032         // ODIM padded to multiple of 8
#define NCOL    65536        // BATCH * SEQL
#define OUTPER  1048576      // SEQL * HOP
#define PAD     384          // (NFFT - HOP)/2
#define TWO_PI  6.283185307179586476925286766559f

// ---------------------------------------------------------------------------
// Scratch (static device globals; no runtime allocation allowed)
// ---------------------------------------------------------------------------
__device__ float g_h[(size_t)ODIM * NCOL];        // linear output  [o][n]      269 MB
__device__ float g_spec[(size_t)KPAD * NCOL];     // [Re;Im;pad]    [k][n]      270 MB
__device__ float g_frames[(size_t)NCOL * NFFT];   // frames         [b*l][n]    268 MB
__device__ float g_twin[(size_t)KPAD * NFFT];     // iDFT*window    [k][n]      4.2 MB

// ---------------------------------------------------------------------------
// Build the windowed inverse-rDFT matrix (transposed: rows k, cols n).
//   frames[n] = w[n]/N * [ Re0 + 2*sum_{1..511}(Re_k cos - Im_k sin) + Re512*(-1)^n ]
// Imag parts of DC/Nyquist multiply real basis functions -> contribute nothing
// to the real output, matching numpy/jax irfft semantics. Angle reduced exactly
// via (k*n) mod 1024 before the float trig call.
// ---------------------------------------------------------------------------
__global__ void gen_twin_kernel() {
    int idx = blockIdx.x * blockDim.x + threadIdx.x;
    if (idx >= KPAD * NFFT) return;
    int k = idx >> 10;
    int n = idx & (NFFT - 1);
    const float inv = 1.0f / (float)NFFT;
    float w = 0.5f * (1.0f - cosf(TWO_PI * (float)n * inv));
    float val = 0.0f;
    if (k < FBINS) {
        float alpha = (k == 0 || k == FBINS - 1) ? 1.0f : 2.0f;
        int m = (k * n) & (NFFT - 1);
        val = alpha * w * cosf(TWO_PI * (float)m * inv) * inv;
    } else if (k < ODIM) {
        int kp = k - FBINS;
        if (kp != 0 && kp != FBINS - 1) {
            int m = (kp * n) & (NFFT - 1);
            val = -2.0f * w * sinf(TWO_PI * (float)m * inv) * inv;
        }
    }
    g_twin[idx] = val;
}

// Zero the padded K-rows of g_spec (rows 1026..1031) so GEMM2 needs no K-guard.
__global__ void zero_pad_kernel() {
    int idx = blockIdx.x * blockDim.x + threadIdx.x;
    if (idx >= (KPAD - ODIM) * NCOL) return;
    g_spec[(size_t)ODIM * NCOL + idx] = 0.0f;
}

// ---------------------------------------------------------------------------
// GEMM1: h[o][n] = sum_d W[o][d] * x[b][d][l] + bias[o]
//   M = 1026 (o), N = 65536 (n = b*4096 + l), K = 512
//   128x128 tile, BK=8, 256 threads, 8x8 per thread.
// ---------------------------------------------------------------------------
__global__ __launch_bounds__(256)
void gemm1_kernel(const float* __restrict__ W, const float* __restrict__ x,
                  const float* __restrict__ bias) {
    __shared__ float As[8][128];
    __shared__ float Bs[8][128];
    const int m0 = blockIdx.x * 128;
    const int n0 = blockIdx.y * 128;
    const int bidx = n0 >> 12;               // 4096 % 128 == 0: single batch per tile
    const int l0 = n0 & (SEQL - 1);
    const float* xb = x + (size_t)bidx * DIM * SEQL + l0;

    const int tid  = threadIdx.x;
    const int arow = tid >> 1;               // 0..127
    const int acol = (tid & 1) * 4;          // 0 or 4
    const int brow = tid >> 5;               // 0..7
    const int bcol = (tid & 31) * 4;         // 0..124
    const int tx = tid & 15, ty = tid >> 4;

    float acc[8][8] = {};

    for (int k0 = 0; k0 < DIM; k0 += 8) {
        float4 av = make_float4(0.f, 0.f, 0.f, 0.f);
        int grow = m0 + arow;
        if (grow < ODIM)
            av = *(const float4*)(W + (size_t)grow * DIM + k0 + acol);
        As[acol + 0][arow] = av.x;
        As[acol + 1][arow] = av.y;
        As[acol + 2][arow] = av.z;
        As[acol + 3][arow] = av.w;

        *(float4*)&Bs[brow][bcol] =
            *(const float4*)(xb + (size_t)(k0 + brow) * SEQL + bcol);
        __syncthreads();

#pragma unroll
        for (int kk = 0; kk < 8; ++kk) {
            float a[8], bb[8];
            *(float4*)(a)      = *(float4*)&As[kk][ty * 8];
            *(float4*)(a + 4)  = *(float4*)&As[kk][ty * 8 + 4];
            *(float4*)(bb)     = *(float4*)&Bs[kk][tx * 8];
            *(float4*)(bb + 4) = *(float4*)&Bs[kk][tx * 8 + 4];
#pragma unroll
            for (int i = 0; i < 8; ++i)
#pragma unroll
                for (int j = 0; j < 8; ++j)
                    acc[i][j] += a[i] * bb[j];
        }
        __syncthreads();
    }

#pragma unroll
    for (int i = 0; i < 8; ++i) {
        int gm = m0 + ty * 8 + i;
        if (gm >= ODIM) break;
        float bv = bias[gm];
        float* hp = g_h + (size_t)gm * NCOL + n0 + tx * 8;
        float4 v0 = make_float4(acc[i][0] + bv, acc[i][1] + bv,
                                acc[i][2] + bv, acc[i][3] + bv);
        float4 v1 = make_float4(acc[i][4] + bv, acc[i][5] + bv,
                                acc[i][6] + bv, acc[i][7] + bv);
        *(float4*)hp       = v0;
        *(float4*)(hp + 4) = v1;
    }
}

// ---------------------------------------------------------------------------
// Elementwise: spec[k]   = min(exp(h[k]),100) * cos(h[k+513])
//              spec[k+513] = min(exp(h[k]),100) * sin(h[k+513])
// ---------------------------------------------------------------------------
__global__ void spectrum_kernel() {
    int idx = blockIdx.x * blockDim.x + threadIdx.x;
    if (idx >= FBINS * NCOL) return;
    int k = idx >> 16;
    int n = idx & (NCOL - 1);
    float mag = fminf(expf(g_h[(size_t)k * NCOL + n]), 100.0f);
    float p = g_h[(size_t)(k + FBINS) * NCOL + n];
    float s, c;
    sincosf(p, &s, &c);
    g_spec[(size_t)k * NCOL + n]           = mag * c;
    g_spec[(size_t)(k + FBINS) * NCOL + n] = mag * s;
}

// ---------------------------------------------------------------------------
// GEMM2 (computes C^T so frames come out [b*l][n] row-major, coalesced):
//   frames[m][n] = sum_k spec[k][m] * twin[k][n]
//   M = 65536 (m = b*4096+l), N = 1024 (n), K = 1032 (padded)
// ---------------------------------------------------------------------------
__global__ __launch_bounds__(256)
void gemm2_kernel() {
    __shared__ float As[8][128];
    __shared__ float Bs[8][128];
    const int m0 = blockIdx.x * 128;
    const int n0 = blockIdx.y * 128;
    const int tid  = threadIdx.x;
    const int krow = tid >> 5;               // 0..7
    const int mcol = (tid & 31) * 4;         // 0..124
    const int tx = tid & 15, ty = tid >> 4;

    float acc[8][8] = {};

    for (int k0 = 0; k0 < KPAD; k0 += 8) {
        *(float4*)&As[krow][mcol] =
            *(const float4*)(g_spec + (size_t)(k0 + krow) * NCOL + m0 + mcol);
        *(float4*)&Bs[krow][mcol] =
            *(const float4*)(g_twin + (size_t)(k0 + krow) * NFFT + n0 + mcol);
        __syncthreads();

#pragma unroll
        for (int kk = 0; kk < 8; ++kk) {
            float a[8], bb[8];
            *(float4*)(a)      = *(float4*)&As[kk][ty * 8];
            *(float4*)(a + 4)  = *(float4*)&As[kk][ty * 8 + 4];
            *(float4*)(bb)     = *(float4*)&Bs[kk][tx * 8];
            *(float4*)(bb + 4) = *(float4*)&Bs[kk][tx * 8 + 4];
#pragma unroll
            for (int i = 0; i < 8; ++i)
#pragma unroll
                for (int j = 0; j < 8; ++j)
                    acc[i][j] += a[i] * bb[j];
        }
        __syncthreads();
    }

#pragma unroll
    for (int i = 0; i < 8; ++i) {
        float* fp = g_frames + (size_t)(m0 + ty * 8 + i) * NFFT + n0 + tx * 8;
        *(float4*)fp       = make_float4(acc[i][0], acc[i][1], acc[i][2], acc[i][3]);
        *(float4*)(fp + 4) = make_float4(acc[i][4], acc[i][5], acc[i][6], acc[i][7]);
    }
}

// ---------------------------------------------------------------------------
// Overlap-add gather + window-square envelope normalization + center trim.
// Each output sample sums <=4 frame contributions; env computed analytically
// with the same frame-validity bounds as the reference scatter-add.
// ---------------------------------------------------------------------------
__global__ void ola_kernel(float* __restrict__ out) {
    int idx = blockIdx.x * blockDim.x + threadIdx.x;
    if (idx >= BATCH * OUTPER) return;
    int b = idx >> 20;                        // OUTPER == 2^20
    int t = idx & (OUTPER - 1);
    int g = t + PAD;
    int lmin = (g - (NFFT - 1) + (HOP - 1)) >> 8;   // ceil((g-1023)/256)
    if (lmin < 0) lmin = 0;
    int lmax = g >> 8;
    if (lmax > SEQL - 1) lmax = SEQL - 1;

    const float* fb = g_frames + (size_t)b * SEQL * NFFT;
    float acc = 0.0f, env = 0.0f;
    const float inv = 1.0f / (float)NFFT;
    for (int l = lmin; l <= lmax; ++l) {
        int n = g - (l << 8);
        float w = 0.5f * (1.0f - cosf(TWO_PI * (float)n * inv));
        acc += fb[(size_t)l * NFFT + n];
        env += w * w;
    }
    out[idx] = acc / (env > 1e-11f ? env : 1.0f);
}

// ---------------------------------------------------------------------------
// Launch
// ---------------------------------------------------------------------------
extern "C" void kernel_launch(void* const* d_in, const int* in_sizes, int n_in,
                              void* d_out, int out_size) {
    const float* x    = (const float*)d_in[0];   // (16, 512, 4096)
    const float* W    = (const float*)d_in[1];   // (1026, 512)
    const float* bias = (const float*)d_in[2];   // (1026,)
    float* out = (float*)d_out;                  // (16, 1048576)

    gen_twin_kernel<<<(KPAD * NFFT + 255) / 256, 256>>>();
    zero_pad_kernel<<<((KPAD - ODIM) * NCOL + 255) / 256, 256>>>();

    gemm1_kernel<<<dim3((ODIM + 127) / 128, NCOL / 128), 256>>>(W, x, bias);

    spectrum_kernel<<<(FBINS * NCOL + 255) / 256, 256>>>();

    gemm2_kernel<<<dim3(NCOL / 128, NFFT / 128), 256>>>();

    ola_kernel<<<(BATCH * OUTPER + 255) / 256, 256>>>(out);
}

// round 3
// speedup vs baseline: 2.6748x; 2.6748x over previous
#include <cuda_runtime.h>
#include <cuda_bf16.h>
#include <cstdint>
#include <math.h>

// Problem constants
#define BATCH   16
#define DIM     512
#define SEQL    4096
#define NFFT    1024
#define HOP     256
#define FBINS   513          // NFFT/2 + 1
#define ODIM    1026         // 2*FBINS
#define KPAD    1056         // ODIM padded to multiple of 32
#define NCOL    65536        // BATCH * SEQL
#define OUTPER  1048576      // SEQL * HOP
#define PAD     384          // (NFFT - HOP)/2
#define TWO_PI  6.283185307179586476925286766559f

// GEMM tiling
#define BM 128
#define BN 256
#define BK 32
#define ASTRIDE 136          // BM + 8  -> conflict-free fragment loads
#define BSTRIDE 264          // BN + 8
#define SMEM_BYTES ((BK*ASTRIDE + BK*BSTRIDE) * 4)   // 51200

// ---------------------------------------------------------------------------
// Scratch (static device globals; no runtime allocation allowed)
// ---------------------------------------------------------------------------
__device__ float g_h[(size_t)ODIM * NCOL];        // linear output  [o][n]
__device__ float g_spec[(size_t)KPAD * NCOL];     // [Re;Im;pad]    [k][n] (tf32-rounded)
__device__ float g_frames[(size_t)NCOL * NFFT];   // frames         [b*l][n]
__device__ float g_twin[(size_t)KPAD * NFFT];     // iDFT*window    [k][n] (tf32-rounded)

// tf32 cvt requires a .b32 destination register ("=r"), result is an fp32
// bit-pattern with the low mantissa bits cleared -> bitcast back is exact.
__device__ __forceinline__ float to_tf32(float x) {
    uint32_t y;
    asm("cvt.rna.tf32.f32 %0, %1;" : "=r"(y) : "f"(x));
    return __uint_as_float(y);
}

__device__ __forceinline__ void mma_tf32(float c[4], const uint32_t a[4], const uint32_t b[2]) {
    asm volatile(
        "mma.sync.aligned.m16n8k8.row.col.f32.tf32.tf32.f32 "
        "{%0,%1,%2,%3}, {%4,%5,%6,%7}, {%8,%9}, {%0,%1,%2,%3};\n"
        : "+f"(c[0]), "+f"(c[1]), "+f"(c[2]), "+f"(c[3])
        : "r"(a[0]), "r"(a[1]), "r"(a[2]), "r"(a[3]), "r"(b[0]), "r"(b[1]));
}

// ---------------------------------------------------------------------------
// Windowed inverse-rDFT matrix (rows k, cols n), values tf32-rounded.
// Imag parts of DC/Nyquist contribute nothing to the real output.
// ---------------------------------------------------------------------------
__global__ void gen_twin_kernel() {
    int idx = blockIdx.x * blockDim.x + threadIdx.x;
    if (idx >= KPAD * NFFT) return;
    int k = idx >> 10;
    int n = idx & (NFFT - 1);
    const float inv = 1.0f / (float)NFFT;
    float w = 0.5f * (1.0f - cosf(TWO_PI * (float)n * inv));
    float val = 0.0f;
    if (k < FBINS) {
        float alpha = (k == 0 || k == FBINS - 1) ? 1.0f : 2.0f;
        int m = (k * n) & (NFFT - 1);
        val = alpha * w * cosf(TWO_PI * (float)m * inv) * inv;
    } else if (k < ODIM) {
        int kp = k - FBINS;
        if (kp != 0 && kp != FBINS - 1) {
            int m = (kp * n) & (NFFT - 1);
            val = -2.0f * w * sinf(TWO_PI * (float)m * inv) * inv;
        }
    }
    g_twin[idx] = to_tf32(val);
}

// Zero the padded K-rows of g_spec (rows 1026..1055) so GEMM2 needs no K-guard.
__global__ void zero_pad_kernel() {
    int idx = blockIdx.x * blockDim.x + threadIdx.x;
    if (idx >= (KPAD - ODIM) * NCOL) return;
    g_spec[(size_t)ODIM * NCOL + idx] = 0.0f;
}

// ---------------------------------------------------------------------------
// GEMM1 (TF32 mma): h[o][n] = sum_d W[o][d] * x[b][d][l] + bias[o]
//   M = 1026 (9 tiles of 128), N = 65536, K = 512
//   grid.x = m-tile (so consecutive blocks share the L2-resident B tile)
// ---------------------------------------------------------------------------
__global__ __launch_bounds__(256, 1)
void gemm1_mma(const float* __restrict__ W, const float* __restrict__ x,
               const float* __restrict__ bias) {
    extern __shared__ float sm[];
    float* As = sm;                    // [BK][ASTRIDE]  (k-major)
    float* Bs = sm + BK * ASTRIDE;     // [BK][BSTRIDE]

    const int m0 = blockIdx.x * BM;
    const int n0 = blockIdx.y * BN;
    const int bidx = n0 >> 12;                 // 256 | 4096 -> single batch per tile
    const int l0 = n0 & (SEQL - 1);
    const float* xb = x + (size_t)bidx * DIM * SEQL + l0;

    const int tid = threadIdx.x;
    const int wid = tid >> 5, lane = tid & 31;
    const int wm = (wid & 1) * 64, wn = (wid >> 1) * 64;
    const int lr = lane >> 2, lc = lane & 3;

    float acc[4][8][4];
#pragma unroll
    for (int i = 0; i < 4; i++)
#pragma unroll
        for (int j = 0; j < 8; j++)
#pragma unroll
            for (int q = 0; q < 4; q++) acc[i][j][q] = 0.0f;

    for (int k0 = 0; k0 < DIM; k0 += BK) {
        // Stage A: transpose-load W[m0..m0+127][k0..k0+31] into As[k][m]
#pragma unroll
        for (int i = 0; i < 4; i++) {
            int idx = tid + 256 * i;
            int m = idx >> 3;
            int k4 = (idx & 7) << 2;
            float4 v = make_float4(0.f, 0.f, 0.f, 0.f);
            if (m0 + m < ODIM)
                v = *(const float4*)(W + (size_t)(m0 + m) * DIM + k0 + k4);
            As[(k4 + 0) * ASTRIDE + m] = to_tf32(v.x);
            As[(k4 + 1) * ASTRIDE + m] = to_tf32(v.y);
            As[(k4 + 2) * ASTRIDE + m] = to_tf32(v.z);
            As[(k4 + 3) * ASTRIDE + m] = to_tf32(v.w);
        }
        // Stage B: x rows (coalesced)
#pragma unroll
        for (int i = 0; i < 8; i++) {
            int idx = tid + 256 * i;
            int r = idx >> 6;
            int c4 = (idx & 63) << 2;
            float4 v = *(const float4*)(xb + (size_t)(k0 + r) * SEQL + c4);
            v.x = to_tf32(v.x); v.y = to_tf32(v.y);
            v.z = to_tf32(v.z); v.w = to_tf32(v.w);
            *(float4*)(Bs + r * BSTRIDE + c4) = v;
        }
        __syncthreads();

#pragma unroll
        for (int k8 = 0; k8 < BK; k8 += 8) {
            uint32_t af[4][4], bf[8][2];
#pragma unroll
            for (int im = 0; im < 4; im++) {
                int rm = wm + im * 16 + lr;
                af[im][0] = __float_as_uint(As[(k8 + lc) * ASTRIDE + rm]);
                af[im][1] = __float_as_uint(As[(k8 + lc) * ASTRIDE + rm + 8]);
                af[im][2] = __float_as_uint(As[(k8 + 4 + lc) * ASTRIDE + rm]);
                af[im][3] = __float_as_uint(As[(k8 + 4 + lc) * ASTRIDE + rm + 8]);
            }
#pragma unroll
            for (int jn = 0; jn < 8; jn++) {
                int cb = wn + jn * 8 + lr;
                bf[jn][0] = __float_as_uint(Bs[(k8 + lc) * BSTRIDE + cb]);
                bf[jn][1] = __float_as_uint(Bs[(k8 + 4 + lc) * BSTRIDE + cb]);
            }
#pragma unroll
            for (int im = 0; im < 4; im++)
#pragma unroll
                for (int jn = 0; jn < 8; jn++)
                    mma_tf32(acc[im][jn], af[im], bf[jn]);
        }
        __syncthreads();
    }

    // Store with bias (guard M)
#pragma unroll
    for (int im = 0; im < 4; im++) {
        int r0 = m0 + wm + im * 16 + lr;
        float bv0 = (r0 < ODIM) ? bias[r0] : 0.0f;
        float bv1 = (r0 + 8 < ODIM) ? bias[r0 + 8] : 0.0f;
#pragma unroll
        for (int jn = 0; jn < 8; jn++) {
            int c = n0 + wn + jn * 8 + 2 * lc;
            if (r0 < ODIM)
                *(float2*)(g_h + (size_t)r0 * NCOL + c) =
                    make_float2(acc[im][jn][0] + bv0, acc[im][jn][1] + bv0);
            if (r0 + 8 < ODIM)
                *(float2*)(g_h + (size_t)(r0 + 8) * NCOL + c) =
                    make_float2(acc[im][jn][2] + bv1, acc[im][jn][3] + bv1);
        }
    }
}

// ---------------------------------------------------------------------------
// Elementwise spectrum: tf32-rounded Re/Im
// ---------------------------------------------------------------------------
__global__ void spectrum_kernel() {
    int idx = blockIdx.x * blockDim.x + threadIdx.x;
    if (idx >= FBINS * NCOL) return;
    int k = idx >> 16;
    int n = idx & (NCOL - 1);
    float mag = fminf(expf(g_h[(size_t)k * NCOL + n]), 100.0f);
    float p = g_h[(size_t)(k + FBINS) * NCOL + n];
    float s, c;
    sincosf(p, &s, &c);
    g_spec[(size_t)k * NCOL + n]           = to_tf32(mag * c);
    g_spec[(size_t)(k + FBINS) * NCOL + n] = to_tf32(mag * s);
}

// ---------------------------------------------------------------------------
// GEMM2 (TF32 mma): frames[m][n] = sum_k spec[k][m] * twin[k][n]
//   M = 65536, N = 1024 (grid.x = 4 n-tiles so the A tile is L2-reused), K = 1056
// ---------------------------------------------------------------------------
__global__ __launch_bounds__(256, 1)
void gemm2_mma() {
    extern __shared__ float sm[];
    float* As = sm;
    float* Bs = sm + BK * ASTRIDE;

    const int m0 = blockIdx.y * BM;
    const int n0 = blockIdx.x * BN;
    const int tid = threadIdx.x;
    const int wid = tid >> 5, lane = tid & 31;
    const int wm = (wid & 1) * 64, wn = (wid >> 1) * 64;
    const int lr = lane >> 2, lc = lane & 3;

    float acc[4][8][4];
#pragma unroll
    for (int i = 0; i < 4; i++)
#pragma unroll
        for (int j = 0; j < 8; j++)
#pragma unroll
            for (int q = 0; q < 4; q++) acc[i][j][q] = 0.0f;

    for (int k0 = 0; k0 < KPAD; k0 += BK) {
        // Stage A (already tf32-rounded, k-major in global -> direct copy)
#pragma unroll
        for (int i = 0; i < 4; i++) {
            int idx = tid + 256 * i;
            int r = idx >> 5;
            int c4 = (idx & 31) << 2;
            float4 v = *(const float4*)(g_spec + (size_t)(k0 + r) * NCOL + m0 + c4);
            *(float4*)(As + r * ASTRIDE + c4) = v;
        }
        // Stage B
#pragma unroll
        for (int i = 0; i < 8; i++) {
            int idx = tid + 256 * i;
            int r = idx >> 6;
            int c4 = (idx & 63) << 2;
            float4 v = *(const float4*)(g_twin + (size_t)(k0 + r) * NFFT + n0 + c4);
            *(float4*)(Bs + r * BSTRIDE + c4) = v;
        }
        __syncthreads();

#pragma unroll
        for (int k8 = 0; k8 < BK; k8 += 8) {
            uint32_t af[4][4], bf[8][2];
#pragma unroll
            for (int im = 0; im < 4; im++) {
                int rm = wm + im * 16 + lr;
                af[im][0] = __float_as_uint(As[(k8 + lc) * ASTRIDE + rm]);
                af[im][1] = __float_as_uint(As[(k8 + lc) * ASTRIDE + rm + 8]);
                af[im][2] = __float_as_uint(As[(k8 + 4 + lc) * ASTRIDE + rm]);
                af[im][3] = __float_as_uint(As[(k8 + 4 + lc) * ASTRIDE + rm + 8]);
            }
#pragma unroll
            for (int jn = 0; jn < 8; jn++) {
                int cb = wn + jn * 8 + lr;
                bf[jn][0] = __float_as_uint(Bs[(k8 + lc) * BSTRIDE + cb]);
                bf[jn][1] = __float_as_uint(Bs[(k8 + 4 + lc) * BSTRIDE + cb]);
            }
#pragma unroll
            for (int im = 0; im < 4; im++)
#pragma unroll
                for (int jn = 0; jn < 8; jn++)
                    mma_tf32(acc[im][jn], af[im], bf[jn]);
        }
        __syncthreads();
    }

#pragma unroll
    for (int im = 0; im < 4; im++) {
        int r0 = m0 + wm + im * 16 + lr;
#pragma unroll
        for (int jn = 0; jn < 8; jn++) {
            int c = n0 + wn + jn * 8 + 2 * lc;
            *(float2*)(g_frames + (size_t)r0 * NFFT + c) =
                make_float2(acc[im][jn][0], acc[im][jn][1]);
            *(float2*)(g_frames + (size_t)(r0 + 8) * NFFT + c) =
                make_float2(acc[im][jn][2], acc[im][jn][3]);
        }
    }
}

// ---------------------------------------------------------------------------
// Overlap-add gather + analytic window-square envelope + center trim.
// ---------------------------------------------------------------------------
__global__ void ola_kernel(float* __restrict__ out) {
    int idx = blockIdx.x * blockDim.x + threadIdx.x;
    if (idx >= BATCH * OUTPER) return;
    int b = idx >> 20;
    int t = idx & (OUTPER - 1);
    int g = t + PAD;
    int lmin = (g - (NFFT - 1) + (HOP - 1)) >> 8;
    if (lmin < 0) lmin = 0;
    int lmax = g >> 8;
    if (lmax > SEQL - 1) lmax = SEQL - 1;

    const float* fb = g_frames + (size_t)b * SEQL * NFFT;
    float acc = 0.0f, env = 0.0f;
    const float inv = 1.0f / (float)NFFT;
    for (int l = lmin; l <= lmax; ++l) {
        int n = g - (l << 8);
        float w = 0.5f * (1.0f - cosf(TWO_PI * (float)n * inv));
        acc += fb[(size_t)l * NFFT + n];
        env += w * w;
    }
    out[idx] = acc / (env > 1e-11f ? env : 1.0f);
}

// ---------------------------------------------------------------------------
// Launch
// ---------------------------------------------------------------------------
extern "C" void kernel_launch(void* const* d_in, const int* in_sizes, int n_in,
                              void* d_out, int out_size) {
    const float* x    = (const float*)d_in[0];   // (16, 512, 4096)
    const float* W    = (const float*)d_in[1];   // (1026, 512)
    const float* bias = (const float*)d_in[2];   // (1026,)
    float* out = (float*)d_out;                  // (16, 1048576)

    // Opt-in to >48KB dynamic smem (host-side config; capture-safe, idempotent)
    cudaFuncSetAttribute(gemm1_mma, cudaFuncAttributeMaxDynamicSharedMemorySize, SMEM_BYTES);
    cudaFuncSetAttribute(gemm2_mma, cudaFuncAttributeMaxDynamicSharedMemorySize, SMEM_BYTES);

    gen_twin_kernel<<<(KPAD * NFFT + 255) / 256, 256>>>();
    zero_pad_kernel<<<((KPAD - ODIM) * NCOL + 255) / 256, 256>>>();

    gemm1_mma<<<dim3((ODIM + BM - 1) / BM, NCOL / BN), 256, SMEM_BYTES>>>(W, x, bias);

    spectrum_kernel<<<(FBINS * NCOL + 255) / 256, 256>>>();

    gemm2_mma<<<dim3(NFFT / BN, NCOL / BM), 256, SMEM_BYTES>>>();

    ola_kernel<<<(BATCH * OUTPER + 255) / 256, 256>>>(out);
}

// round 4
// speedup vs baseline: 3.5251x; 1.3179x over previous
#include <cuda_runtime.h>
#include <cuda_bf16.h>
#include <cstdint>
#include <math.h>

// Problem constants
#define BATCH   16
#define DIM     512
#define SEQL    4096
#define NFFT    1024
#define HOP     256
#define FBINS   513          // NFFT/2 + 1
#define ODIM    1026         // 2*FBINS
#define KPAD    1056         // ODIM padded to multiple of 32
#define NCOL    65536        // BATCH * SEQL
#define OUTPER  1048576      // SEQL * HOP
#define PAD     384          // (NFFT - HOP)/2
#define TWO_PI  6.283185307179586476925286766559f

// Permuted-W layout: tiles of 16 rows = {8 mag bins, same 8 phase bins}
#define MPERM   1152         // 72 tiles * 16 rows, 9 block-tiles of 128

// GEMM tiling
#define BM 128
#define BN 256
#define BK 32
#define ASTRIDE 136          // BM + 8  (rows stay 16B-aligned: 136*4=544)
#define BSTRIDE 264          // BN + 8  (264*4=1056)
#define A_WORDS (BK * ASTRIDE)           // 4352
#define B_WORDS (BK * BSTRIDE)           // 8448
#define STAGE_WORDS (A_WORDS + B_WORDS)  // 12800
#define SMEM_BYTES (2 * STAGE_WORDS * 4) // 102400 (double buffered)

// ---------------------------------------------------------------------------
// Scratch (static device globals; no runtime allocation allowed)
// ---------------------------------------------------------------------------
__device__ float g_spec[(size_t)KPAD * NCOL];       // [Re;Im;pad] [k][n] tf32
__device__ float g_frames[(size_t)NCOL * NFFT];     // frames [b*l][n]
__device__ float g_twin[(size_t)KPAD * NFFT];       // iDFT*window [k][n] tf32
__device__ float g_xr[(size_t)BATCH * DIM * SEQL];  // tf32-rounded x
__device__ float g_Wp[(size_t)DIM * MPERM];         // permuted W, k-major, tf32

__device__ __forceinline__ float to_tf32(float x) {
    uint32_t y;
    asm("cvt.rna.tf32.f32 %0, %1;" : "=r"(y) : "f"(x));
    return __uint_as_float(y);
}

__device__ __forceinline__ void mma_tf32(float c[4], const uint32_t a[4], const uint32_t b[2]) {
    asm volatile(
        "mma.sync.aligned.m16n8k8.row.col.f32.tf32.tf32.f32 "
        "{%0,%1,%2,%3}, {%4,%5,%6,%7}, {%8,%9}, {%0,%1,%2,%3};\n"
        : "+f"(c[0]), "+f"(c[1]), "+f"(c[2]), "+f"(c[3])
        : "r"(a[0]), "r"(a[1]), "r"(a[2]), "r"(a[3]), "r"(b[0]), "r"(b[1]));
}

#define CP_ASYNC_CG(dst_u32, src_ptr) \
    asm volatile("cp.async.cg.shared.global [%0], [%1], 16;\n" \
                 :: "r"(dst_u32), "l"(src_ptr))
#define CP_COMMIT() asm volatile("cp.async.commit_group;\n")
#define CP_WAIT1()  asm volatile("cp.async.wait_group 1;\n")
#define CP_WAIT0()  asm volatile("cp.async.wait_group 0;\n")

// ---------------------------------------------------------------------------
// Prep kernels
// ---------------------------------------------------------------------------
// Windowed inverse-rDFT matrix (rows k, cols n), tf32-rounded.
__global__ void gen_twin_kernel() {
    int idx = blockIdx.x * blockDim.x + threadIdx.x;
    if (idx >= KPAD * NFFT) return;
    int k = idx >> 10;
    int n = idx & (NFFT - 1);
    const float inv = 1.0f / (float)NFFT;
    float w = 0.5f * (1.0f - cosf(TWO_PI * (float)n * inv));
    float val = 0.0f;
    if (k < FBINS) {
        float alpha = (k == 0 || k == FBINS - 1) ? 1.0f : 2.0f;
        int m = (k * n) & (NFFT - 1);
        val = alpha * w * cosf(TWO_PI * (float)m * inv) * inv;
    } else if (k < ODIM) {
        int kp = k - FBINS;
        if (kp != 0 && kp != FBINS - 1) {
            int m = (kp * n) & (NFFT - 1);
            val = -2.0f * w * sinf(TWO_PI * (float)m * inv) * inv;
        }
    }
    g_twin[idx] = to_tf32(val);
}

// Zero padded K-rows of g_spec (rows 1026..1055).
__global__ void zero_pad_kernel() {
    int idx = blockIdx.x * blockDim.x + threadIdx.x;
    if (idx >= (KPAD - ODIM) * NCOL) return;
    g_spec[(size_t)ODIM * NCOL + idx] = 0.0f;
}

// Permute + transpose + tf32-round W into g_Wp[k][m'] (k-major).
// Tile t of 16 rows: rows 0-7 = mag bins t*8..t*8+7 (W rows bin),
//                    rows 8-15 = phase of same bins (W rows 513+bin).
__global__ void wperm_kernel(const float* __restrict__ W) {
    int idx = blockIdx.x * blockDim.x + threadIdx.x;
    if (idx >= DIM * MPERM) return;
    int k = idx / MPERM;
    int mp = idx - k * MPERM;
    int tile = mp >> 4, w = mp & 15;
    int bin = tile * 8 + (w & 7);
    float val = 0.0f;
    if (bin < FBINS) {
        int o = (w < 8) ? bin : (FBINS + bin);
        val = to_tf32(W[(size_t)o * DIM + k]);
    }
    g_Wp[idx] = val;
}

// tf32-round x into g_xr (vectorized).
__global__ void xround_kernel(const float* __restrict__ x) {
    int idx = blockIdx.x * blockDim.x + threadIdx.x;
    if (idx >= BATCH * DIM * SEQL / 4) return;
    float4 v = ((const float4*)x)[idx];
    v.x = to_tf32(v.x); v.y = to_tf32(v.y);
    v.z = to_tf32(v.z); v.w = to_tf32(v.w);
    ((float4*)g_xr)[idx] = v;
}

// ---------------------------------------------------------------------------
// GEMM1 (TF32 mma, cp.async double-buffered, fused spectrum epilogue):
//   h[m'][n] = sum_k Wp[k][m'] * xr[b][k][l],  then per bin pair:
//   spec[bin] = min(exp(h_mag+b),100)*cos(h_ph+b'); spec[bin+513] = ...sin...
//   M' = 1152, N = 65536, K = 512
// ---------------------------------------------------------------------------
__global__ __launch_bounds__(256, 1)
void gemm1_mma(const float* __restrict__ bias) {
    extern __shared__ float sm[];
    const uint32_t smem_u32 = (uint32_t)__cvta_generic_to_shared(sm);

    const int m0 = blockIdx.x * BM;
    const int n0 = blockIdx.y * BN;
    const int bidx = n0 >> 12;
    const int l0 = n0 & (SEQL - 1);
    const float* xb = g_xr + (size_t)bidx * DIM * SEQL + l0;

    const int tid = threadIdx.x;
    const int wid = tid >> 5, lane = tid & 31;
    const int wm = (wid & 1) * 64, wn = (wid >> 1) * 64;
    const int lr = lane >> 2, lc = lane & 3;

    float acc[4][8][4];
#pragma unroll
    for (int i = 0; i < 4; i++)
#pragma unroll
        for (int j = 0; j < 8; j++)
#pragma unroll
            for (int q = 0; q < 4; q++) acc[i][j][q] = 0.0f;

    const int T = DIM / BK;   // 16

    auto load_stage = [&](int s) {
        const int k0 = s * BK;
        const uint32_t a_base = smem_u32 + (s & 1) * (STAGE_WORDS * 4);
        const uint32_t b_base = a_base + A_WORDS * 4;
#pragma unroll
        for (int i = 0; i < 4; i++) {                 // A: 32 rows x 128 floats
            int ch = tid + 256 * i;
            int r = ch >> 5, c16 = ch & 31;
            CP_ASYNC_CG(a_base + (r * ASTRIDE + c16 * 4) * 4,
                        g_Wp + (size_t)(k0 + r) * MPERM + m0 + c16 * 4);
        }
#pragma unroll
        for (int i = 0; i < 8; i++) {                 // B: 32 rows x 256 floats
            int ch = tid + 256 * i;
            int r = ch >> 6, c16 = ch & 63;
            CP_ASYNC_CG(b_base + (r * BSTRIDE + c16 * 4) * 4,
                        xb + (size_t)(k0 + r) * SEQL + c16 * 4);
        }
        CP_COMMIT();
    };

    load_stage(0);
    for (int s = 0; s < T; s++) {
        if (s + 1 < T) { load_stage(s + 1); CP_WAIT1(); } else { CP_WAIT0(); }
        __syncthreads();
        const float* As = sm + (s & 1) * STAGE_WORDS;
        const float* Bs = As + A_WORDS;
#pragma unroll
        for (int k8 = 0; k8 < BK; k8 += 8) {
            uint32_t af[4][4], bf[8][2];
#pragma unroll
            for (int im = 0; im < 4; im++) {
                int rm = wm + im * 16 + lr;
                af[im][0] = __float_as_uint(As[(k8 + lc) * ASTRIDE + rm]);
                af[im][1] = __float_as_uint(As[(k8 + lc) * ASTRIDE + rm + 8]);
                af[im][2] = __float_as_uint(As[(k8 + 4 + lc) * ASTRIDE + rm]);
                af[im][3] = __float_as_uint(As[(k8 + 4 + lc) * ASTRIDE + rm + 8]);
            }
#pragma unroll
            for (int jn = 0; jn < 8; jn++) {
                int cb = wn + jn * 8 + lr;
                bf[jn][0] = __float_as_uint(Bs[(k8 + lc) * BSTRIDE + cb]);
                bf[jn][1] = __float_as_uint(Bs[(k8 + 4 + lc) * BSTRIDE + cb]);
            }
#pragma unroll
            for (int im = 0; im < 4; im++)
#pragma unroll
                for (int jn = 0; jn < 8; jn++)
                    mma_tf32(acc[im][jn], af[im], bf[jn]);
        }
        __syncthreads();
    }

    // Fused spectrum epilogue: rows r0 (mag) and r0+8 (phase) are the SAME bin.
#pragma unroll
    for (int im = 0; im < 4; im++) {
        int mp = m0 + wm + im * 16 + lr;          // mp & 15 == lr < 8
        int bin = (mp >> 4) * 8 + (mp & 7);
        if (bin < FBINS) {
            float bmag = bias[bin];
            float bph  = bias[FBINS + bin];
#pragma unroll
            for (int jn = 0; jn < 8; jn++) {
                int c = n0 + wn + jn * 8 + 2 * lc;
                float m0v = fminf(expf(acc[im][jn][0] + bmag), 100.0f);
                float m1v = fminf(expf(acc[im][jn][1] + bmag), 100.0f);
                float s0, c0, s1, c1;
                sincosf(acc[im][jn][2] + bph, &s0, &c0);
                sincosf(acc[im][jn][3] + bph, &s1, &c1);
                *(float2*)(g_spec + (size_t)bin * NCOL + c) =
                    make_float2(to_tf32(m0v * c0), to_tf32(m1v * c1));
                *(float2*)(g_spec + (size_t)(FBINS + bin) * NCOL + c) =
                    make_float2(to_tf32(m0v * s0), to_tf32(m1v * s1));
            }
        }
    }
}

// ---------------------------------------------------------------------------
// GEMM2 (TF32 mma, cp.async double-buffered):
//   frames[m][n] = sum_k spec[k][m] * twin[k][n]
//   M = 65536, N = 1024 (grid.x = 4 n-tiles -> A tile L2-reused), K = 1056
// ---------------------------------------------------------------------------
__global__ __launch_bounds__(256, 1)
void gemm2_mma() {
    extern __shared__ float sm[];
    const uint32_t smem_u32 = (uint32_t)__cvta_generic_to_shared(sm);

    const int m0 = blockIdx.y * BM;
    const int n0 = blockIdx.x * BN;
    const int tid = threadIdx.x;
    const int wid = tid >> 5, lane = tid & 31;
    const int wm = (wid & 1) * 64, wn = (wid >> 1) * 64;
    const int lr = lane >> 2, lc = lane & 3;

    float acc[4][8][4];
#pragma unroll
    for (int i = 0; i < 4; i++)
#pragma unroll
        for (int j = 0; j < 8; j++)
#pragma unroll
            for (int q = 0; q < 4; q++) acc[i][j][q] = 0.0f;

    const int T = KPAD / BK;   // 33

    auto load_stage = [&](int s) {
        const int k0 = s * BK;
        const uint32_t a_base = smem_u32 + (s & 1) * (STAGE_WORDS * 4);
        const uint32_t b_base = a_base + A_WORDS * 4;
#pragma unroll
        for (int i = 0; i < 4; i++) {
            int ch = tid + 256 * i;
            int r = ch >> 5, c16 = ch & 31;
            CP_ASYNC_CG(a_base + (r * ASTRIDE + c16 * 4) * 4,
                        g_spec + (size_t)(k0 + r) * NCOL + m0 + c16 * 4);
        }
#pragma unroll
        for (int i = 0; i < 8; i++) {
            int ch = tid + 256 * i;
            int r = ch >> 6, c16 = ch & 63;
            CP_ASYNC_CG(b_base + (r * BSTRIDE + c16 * 4) * 4,
                        g_twin + (size_t)(k0 + r) * NFFT + n0 + c16 * 4);
        }
        CP_COMMIT();
    };

    load_stage(0);
    for (int s = 0; s < T; s++) {
        if (s + 1 < T) { load_stage(s + 1); CP_WAIT1(); } else { CP_WAIT0(); }
        __syncthreads();
        const float* As = sm + (s & 1) * STAGE_WORDS;
        const float* Bs = As + A_WORDS;
#pragma unroll
        for (int k8 = 0; k8 < BK; k8 += 8) {
            uint32_t af[4][4], bf[8][2];
#pragma unroll
            for (int im = 0; im < 4; im++) {
                int rm = wm + im * 16 + lr;
                af[im][0] = __float_as_uint(As[(k8 + lc) * ASTRIDE + rm]);
                af[im][1] = __float_as_uint(As[(k8 + lc) * ASTRIDE + rm + 8]);
                af[im][2] = __float_as_uint(As[(k8 + 4 + lc) * ASTRIDE + rm]);
                af[im][3] = __float_as_uint(As[(k8 + 4 + lc) * ASTRIDE + rm + 8]);
            }
#pragma unroll
            for (int jn = 0; jn < 8; jn++) {
                int cb = wn + jn * 8 + lr;
                bf[jn][0] = __float_as_uint(Bs[(k8 + lc) * BSTRIDE + cb]);
                bf[jn][1] = __float_as_uint(Bs[(k8 + 4 + lc) * BSTRIDE + cb]);
            }
#pragma unroll
            for (int im = 0; im < 4; im++)
#pragma unroll
                for (int jn = 0; jn < 8; jn++)
                    mma_tf32(acc[im][jn], af[im], bf[jn]);
        }
        __syncthreads();
    }

#pragma unroll
    for (int im = 0; im < 4; im++) {
        int r0 = m0 + wm + im * 16 + lr;
#pragma unroll
        for (int jn = 0; jn < 8; jn++) {
            int c = n0 + wn + jn * 8 + 2 * lc;
            *(float2*)(g_frames + (size_t)r0 * NFFT + c) =
                make_float2(acc[im][jn][0], acc[im][jn][1]);
            *(float2*)(g_frames + (size_t)(r0 + 8) * NFFT + c) =
                make_float2(acc[im][jn][2], acc[im][jn][3]);
        }
    }
}

// ---------------------------------------------------------------------------
// Overlap-add gather + analytic window-square envelope + center trim.
// ---------------------------------------------------------------------------
__global__ void ola_kernel(float* __restrict__ out) {
    int idx = blockIdx.x * blockDim.x + threadIdx.x;
    if (idx >= BATCH * OUTPER) return;
    int b = idx >> 20;
    int t = idx & (OUTPER - 1);
    int g = t + PAD;
    int lmin = (g - (NFFT - 1) + (HOP - 1)) >> 8;
    if (lmin < 0) lmin = 0;
    int lmax = g >> 8;
    if (lmax > SEQL - 1) lmax = SEQL - 1;

    const float* fb = g_frames + (size_t)b * SEQL * NFFT;
    float acc = 0.0f, env = 0.0f;
    const float inv = 1.0f / (float)NFFT;
    for (int l = lmin; l <= lmax; ++l) {
        int n = g - (l << 8);
        float w = 0.5f * (1.0f - cosf(TWO_PI * (float)n * inv));
        acc += fb[(size_t)l * NFFT + n];
        env += w * w;
    }
    out[idx] = acc / (env > 1e-11f ? env : 1.0f);
}

// ---------------------------------------------------------------------------
// Launch
// ---------------------------------------------------------------------------
extern "C" void kernel_launch(void* const* d_in, const int* in_sizes, int n_in,
                              void* d_out, int out_size) {
    const float* x    = (const float*)d_in[0];   // (16, 512, 4096)
    const float* W    = (const float*)d_in[1];   // (1026, 512)
    const float* bias = (const float*)d_in[2];   // (1026,)
    float* out = (float*)d_out;                  // (16, 1048576)

    cudaFuncSetAttribute(gemm1_mma, cudaFuncAttributeMaxDynamicSharedMemorySize, SMEM_BYTES);
    cudaFuncSetAttribute(gemm2_mma, cudaFuncAttributeMaxDynamicSharedMemorySize, SMEM_BYTES);

    gen_twin_kernel<<<(KPAD * NFFT + 255) / 256, 256>>>();
    zero_pad_kernel<<<((KPAD - ODIM) * NCOL + 255) / 256, 256>>>();
    wperm_kernel<<<(DIM * MPERM + 255) / 256, 256>>>(W);
    xround_kernel<<<(BATCH * DIM * SEQL / 4 + 255) / 256, 256>>>(x);

    gemm1_mma<<<dim3(MPERM / BM, NCOL / BN), 256, SMEM_BYTES>>>(bias);

    gemm2_mma<<<dim3(NFFT / BN, NCOL / BM), 256, SMEM_BYTES>>>();

    ola_kernel<<<(BATCH * OUTPER + 255) / 256, 256>>>(out);
}

// round 7
// speedup vs baseline: 4.0161x; 1.1393x over previous
#include <cuda_runtime.h>
#include <cuda_bf16.h>
#include <cstdint>
#include <math.h>

// Problem constants
#define BATCH   16
#define DIM     512
#define SEQL    4096
#define NFFT    1024
#define HOP     256
#define FBINS   513          // NFFT/2 + 1
#define NCOL    65536        // BATCH * SEQL
#define OUTPER  1048576      // SEQL * HOP
#define PAD     384          // (NFFT - HOP)/2
#define TWO_PI  6.283185307179586476925286766559f

// spec_T K layout: [Re: 0..512][pad][Im: 544..1056][pad]
#define KR      544
#define KTOT    1088

// Permuted-W layout for GEMM1: tiles of 16 rows = {8 mag bins, same 8 phase bins}
#define MPERM   1152

// GEMM1 (mma.sync) tiling
#define BM 128
#define BN 256
#define BK 32
#define ASTRIDE 136
#define BSTRIDE 264
#define A_WORDS (BK * ASTRIDE)
#define B_WORDS (BK * BSTRIDE)
#define STAGE_WORDS (A_WORDS + B_WORDS)
#define SMEM_BYTES (2 * STAGE_WORDS * 4)   // 102400

// ---------------------------------------------------------------------------
// Scratch (static device globals)
// ---------------------------------------------------------------------------
__device__ float g_specT[(size_t)NCOL * KTOT];      // spec m-major [m][k], fp32
__device__ float g_frames[(size_t)NCOL * NFFT];     // frames [m][n]
__device__ float g_xr[(size_t)BATCH * DIM * SEQL];  // tf32-rounded x (k-major)
__device__ float g_Wp[(size_t)DIM * MPERM];         // permuted W, k-major, tf32
__device__ float2 g_tw[512];                        // exp(+2*pi*i*a/1024)
__device__ float  g_winS[NFFT];                     // hann[n] / 1024

__device__ __forceinline__ float to_tf32(float x) {
    uint32_t y;
    asm("cvt.rna.tf32.f32 %0, %1;" : "=r"(y) : "f"(x));
    return __uint_as_float(y);
}

__device__ __forceinline__ void mma_tf32(float c[4], const uint32_t a[4], const uint32_t b[2]) {
    asm volatile(
        "mma.sync.aligned.m16n8k8.row.col.f32.tf32.tf32.f32 "
        "{%0,%1,%2,%3}, {%4,%5,%6,%7}, {%8,%9}, {%0,%1,%2,%3};\n"
        : "+f"(c[0]), "+f"(c[1]), "+f"(c[2]), "+f"(c[3])
        : "r"(a[0]), "r"(a[1]), "r"(a[2]), "r"(a[3]), "r"(b[0]), "r"(b[1]));
}

#define CP_ASYNC_CG(dst_u32, src_ptr) \
    asm volatile("cp.async.cg.shared.global [%0], [%1], 16;\n" \
                 :: "r"(dst_u32), "l"(src_ptr))
#define CP_COMMIT() asm volatile("cp.async.commit_group;\n")
#define CP_WAIT1()  asm volatile("cp.async.wait_group 1;\n")
#define CP_WAIT0()  asm volatile("cp.async.wait_group 0;\n")

// ---------------------------------------------------------------------------
// Prep kernels
// ---------------------------------------------------------------------------
// Twiddle table exp(+2*pi*i*a/1024) (a<512) + scaled hann window.
__global__ void gen_tables_kernel() {
    int i = blockIdx.x * blockDim.x + threadIdx.x;
    if (i < 512) {
        float s, c;
        sincosf(TWO_PI * (float)i * (1.0f / 1024.0f), &s, &c);
        g_tw[i] = make_float2(c, s);
    }
    if (i < NFFT) {
        float w = 0.5f * (1.0f - cosf(TWO_PI * (float)i * (1.0f / 1024.0f)));
        g_winS[i] = w * (1.0f / 1024.0f);
    }
}

// Permute + transpose + tf32-round W into g_Wp[k][m'] (k-major).
__global__ void wperm_kernel(const float* __restrict__ W) {
    int idx = blockIdx.x * blockDim.x + threadIdx.x;
    if (idx >= DIM * MPERM) return;
    int k = idx / MPERM;
    int mp = idx - k * MPERM;
    int tile = mp >> 4, w = mp & 15;
    int bin = tile * 8 + (w & 7);
    float val = 0.0f;
    if (bin < FBINS) {
        int o = (w < 8) ? bin : (FBINS + bin);
        val = to_tf32(W[(size_t)o * DIM + k]);
    }
    g_Wp[idx] = val;
}

// tf32-round x (vectorized, layout unchanged)
__global__ void xround_kernel(const float* __restrict__ x) {
    int idx = blockIdx.x * blockDim.x + threadIdx.x;
    if (idx >= BATCH * DIM * SEQL / 4) return;
    float4 v = ((const float4*)x)[idx];
    v.x = to_tf32(v.x); v.y = to_tf32(v.y);
    v.z = to_tf32(v.z); v.w = to_tf32(v.w);
    ((float4*)g_xr)[idx] = v;
}

// ---------------------------------------------------------------------------
// GEMM1 (TF32 mma.sync, cp.async double-buffered, fused spectrum epilogue
// that writes spec_T[m][k] m-major via smem transpose):
//   h[m'][n] = sum_k Wp[k][m'] * xr[b][k][l]
// ---------------------------------------------------------------------------
__global__ __launch_bounds__(256, 1)
void gemm1_mma(const float* __restrict__ bias) {
    extern __shared__ float sm[];
    const uint32_t smem_u32 = (uint32_t)__cvta_generic_to_shared(sm);

    const int m0 = blockIdx.x * BM;
    const int n0 = blockIdx.y * BN;
    const int bidx = n0 >> 12;
    const int l0 = n0 & (SEQL - 1);
    const float* xb = g_xr + (size_t)bidx * DIM * SEQL + l0;

    const int tid = threadIdx.x;
    const int wid = tid >> 5, lane = tid & 31;
    const int wm = (wid & 1) * 64, wn = (wid >> 1) * 64;
    const int lr = lane >> 2, lc = lane & 3;

    float acc[4][8][4];
#pragma unroll
    for (int i = 0; i < 4; i++)
#pragma unroll
        for (int j = 0; j < 8; j++)
#pragma unroll
            for (int q = 0; q < 4; q++) acc[i][j][q] = 0.0f;

    const int T = DIM / BK;   // 16

    auto load_stage = [&](int s) {
        const int k0 = s * BK;
        const uint32_t a_base = smem_u32 + (s & 1) * (STAGE_WORDS * 4);
        const uint32_t b_base = a_base + A_WORDS * 4;
#pragma unroll
        for (int i = 0; i < 4; i++) {
            int ch = tid + 256 * i;
            int r = ch >> 5, c16 = ch & 31;
            CP_ASYNC_CG(a_base + (r * ASTRIDE + c16 * 4) * 4,
                        g_Wp + (size_t)(k0 + r) * MPERM + m0 + c16 * 4);
        }
#pragma unroll
        for (int i = 0; i < 8; i++) {
            int ch = tid + 256 * i;
            int r = ch >> 6, c16 = ch & 63;
            CP_ASYNC_CG(b_base + (r * BSTRIDE + c16 * 4) * 4,
                        xb + (size_t)(k0 + r) * SEQL + c16 * 4);
        }
        CP_COMMIT();
    };

    load_stage(0);
    for (int s = 0; s < T; s++) {
        if (s + 1 < T) { load_stage(s + 1); CP_WAIT1(); } else { CP_WAIT0(); }
        __syncthreads();
        const float* As = sm + (s & 1) * STAGE_WORDS;
        const float* Bs = As + A_WORDS;
#pragma unroll
        for (int k8 = 0; k8 < BK; k8 += 8) {
            uint32_t af[4][4], bf[8][2];
#pragma unroll
            for (int im = 0; im < 4; im++) {
                int rm = wm + im * 16 + lr;
                af[im][0] = __float_as_uint(As[(k8 + lc) * ASTRIDE + rm]);
                af[im][1] = __float_as_uint(As[(k8 + lc) * ASTRIDE + rm + 8]);
                af[im][2] = __float_as_uint(As[(k8 + 4 + lc) * ASTRIDE + rm]);
                af[im][3] = __float_as_uint(As[(k8 + 4 + lc) * ASTRIDE + rm + 8]);
            }
#pragma unroll
            for (int jn = 0; jn < 8; jn++) {
                int cb = wn + jn * 8 + lr;
                bf[jn][0] = __float_as_uint(Bs[(k8 + lc) * BSTRIDE + cb]);
                bf[jn][1] = __float_as_uint(Bs[(k8 + 4 + lc) * BSTRIDE + cb]);
            }
#pragma unroll
            for (int im = 0; im < 4; im++)
#pragma unroll
                for (int jn = 0; jn < 8; jn++)
                    mma_tf32(acc[im][jn], af[im], bf[jn]);
        }
        __syncthreads();
    }

    // ---- Fused spectrum epilogue, transposed to spec_T[m][k] ----
    const int TS = 136;
    float* Tt = sm;                        // 128 x 136 floats
    const int bin0 = blockIdx.x * 64;
    int width = FBINS - bin0; if (width > 64) width = 64; if (width < 0) width = 0;

    for (int h = 0; h < 2; h++) {
        if ((wn >> 7) == h) {
            int cbase = wn & 127;
#pragma unroll
            for (int im = 0; im < 4; im++) {
                int bin_l = ((wm >> 4) + im) * 8 + lr;     // 0..63
                int bin = bin0 + bin_l;
                float bmag = (bin < FBINS) ? bias[bin] : 0.0f;
                float bph  = (bin < FBINS) ? bias[FBINS + bin] : 0.0f;
#pragma unroll
                for (int jn = 0; jn < 8; jn++) {
                    int c_l = cbase + jn * 8 + 2 * lc;
                    float m0v = fminf(expf(acc[im][jn][0] + bmag), 100.0f);
                    float m1v = fminf(expf(acc[im][jn][1] + bmag), 100.0f);
                    float s0, c0, s1, c1;
                    sincosf(acc[im][jn][2] + bph, &s0, &c0);
                    sincosf(acc[im][jn][3] + bph, &s1, &c1);
                    Tt[c_l * TS + bin_l]            = m0v * c0;
                    Tt[(c_l + 1) * TS + bin_l]      = m1v * c1;
                    Tt[c_l * TS + 64 + bin_l]       = m0v * s0;
                    Tt[(c_l + 1) * TS + 64 + bin_l] = m1v * s1;
                }
            }
        }
        __syncthreads();
        for (int sidx = wid; sidx < 256; sidx += 8) {
            int c_l = sidx >> 1, part = sidx & 1;
            int m_glob = n0 + h * 128 + c_l;
            float* dst = g_specT + (size_t)m_glob * KTOT + (part ? (KR + bin0) : bin0);
            const float* src = Tt + c_l * TS + part * 64;
            if (lane < width)      dst[lane]      = src[lane];
            if (lane + 32 < width) dst[lane + 32] = src[lane + 32];
        }
        __syncthreads();
    }
}

// ---------------------------------------------------------------------------
// Per-frame 1024-point inverse FFT (radix-2 Stockham autosort, 10 stages).
//   Hermitian-extend spec_T[m] -> complex X[1024]; X <- IDFT(X) (sign +,
//   unnormalized, natural order); frames[m][n] = Re(X[n]) * hann[n]/1024.
// One frame per block, 256 threads, 2 butterflies/thread/stage.
// ---------------------------------------------------------------------------
__global__ __launch_bounds__(256)
void ifft_kernel() {
    __shared__ float2 bufA[1024];
    __shared__ float2 bufB[1024];
    const int m = blockIdx.x;
    const int tid = threadIdx.x;
    const float* src = g_specT + (size_t)m * KTOT;

    // Load + Hermitian extension
#pragma unroll
    for (int h = 0; h < 2; h++) {
        int j = tid + h * 256;                 // 0..511
        float re = src[j];
        float im = src[KR + j];
        bufA[j] = make_float2(re, im);
        if (j > 0) bufA[1024 - j] = make_float2(re, -im);
    }
    if (tid == 0)
        bufA[512] = make_float2(src[512], src[KR + 512]);
    __syncthreads();

    float2* X = bufA;
    float2* Y = bufB;
#pragma unroll
    for (int st = 0; st < 10; st++) {
        const int s = 1 << st;
#pragma unroll
        for (int h = 0; h < 2; h++) {
            int i = tid + h * 256;             // butterfly id 0..511
            int p = i >> st;
            int o0 = (i & (s - 1)) + (p << (st + 1));
            float2 a = X[i];
            float2 b = X[i + 512];
            float2 w = g_tw[p << st];
            Y[o0] = make_float2(a.x + b.x, a.y + b.y);
            float dx = a.x - b.x, dy = a.y - b.y;
            Y[o0 + s] = make_float2(dx * w.x - dy * w.y,
                                    dx * w.y + dy * w.x);
        }
        __syncthreads();
        float2* t = X; X = Y; Y = t;
    }
    // 10 swaps -> result back in bufA (== X), natural order
    float* dst = g_frames + (size_t)m * NFFT;
#pragma unroll
    for (int h = 0; h < 4; h++) {
        int n = tid + h * 256;
        dst[n] = X[n].x * g_winS[n];
    }
}

// ---------------------------------------------------------------------------
// Overlap-add gather + analytic window-square envelope + center trim.
// ---------------------------------------------------------------------------
__global__ void ola_kernel(float* __restrict__ out) {
    int idx = blockIdx.x * blockDim.x + threadIdx.x;
    if (idx >= BATCH * OUTPER) return;
    int b = idx >> 20;
    int t = idx & (OUTPER - 1);
    int g = t + PAD;
    int lmin = (g - (NFFT - 1) + (HOP - 1)) >> 8;
    if (lmin < 0) lmin = 0;
    int lmax = g >> 8;
    if (lmax > SEQL - 1) lmax = SEQL - 1;

    const float* fb = g_frames + (size_t)b * SEQL * NFFT;
    float acc = 0.0f, env = 0.0f;
    const float inv = 1.0f / (float)NFFT;
    for (int l = lmin; l <= lmax; ++l) {
        int n = g - (l << 8);
        float w = 0.5f * (1.0f - cosf(TWO_PI * (float)n * inv));
        acc += fb[(size_t)l * NFFT + n];
        env += w * w;
    }
    out[idx] = acc / (env > 1e-11f ? env : 1.0f);
}

// ---------------------------------------------------------------------------
// Launch
// ---------------------------------------------------------------------------
extern "C" void kernel_launch(void* const* d_in, const int* in_sizes, int n_in,
                              void* d_out, int out_size) {
    const float* x    = (const float*)d_in[0];   // (16, 512, 4096)
    const float* W    = (const float*)d_in[1];   // (1026, 512)
    const float* bias = (const float*)d_in[2];   // (1026,)
    float* out = (float*)d_out;                  // (16, 1048576)

    cudaFuncSetAttribute(gemm1_mma, cudaFuncAttributeMaxDynamicSharedMemorySize, SMEM_BYTES);

    gen_tables_kernel<<<4, 256>>>();
    wperm_kernel<<<(DIM * MPERM + 255) / 256, 256>>>(W);
    xround_kernel<<<(BATCH * DIM * SEQL / 4 + 255) / 256, 256>>>(x);

    gemm1_mma<<<dim3(MPERM / BM, NCOL / BN), 256, SMEM_BYTES>>>(bias);

    ifft_kernel<<<NCOL, 256>>>();

    ola_kernel<<<(BATCH * OUTPER + 255) / 256, 256>>>(out);
}

// round 9
// speedup vs baseline: 4.8307x; 1.2028x over previous
#include <cuda_runtime.h>
#include <cuda_bf16.h>
#include <cstdint>
#include <math.h>

// Problem constants
#define BATCH   16
#define DIM     512
#define SEQL    4096
#define NFFT    1024
#define HOP     256
#define FBINS   513          // NFFT/2 + 1
#define NCOL    65536        // BATCH * SEQL
#define OUTPER  1048576      // SEQL * HOP
#define PAD     384          // (NFFT - HOP)/2
#define TWO_PI  6.283185307179586476925286766559f

// spec_T K layout: [Re: 0..512][pad][Im: 544..1056][pad]
#define KR      544
#define KTOT    1088

// Permuted-W layout for GEMM1: tiles of 16 rows = {8 mag bins, same 8 phase bins}
#define MPERM   1152

// GEMM1 (mma.sync) tiling: block 128x256, 512 threads, warp tile 64x32 (2x8 grid)
#define BM 128
#define BN 256
#define BK 32
#define NTHR 512
#define ASTRIDE 136
#define BSTRIDE 264
#define A_WORDS (BK * ASTRIDE)
#define B_WORDS (BK * BSTRIDE)
#define STAGE_WORDS (A_WORDS + B_WORDS)
#define SMEM_BYTES (2 * STAGE_WORDS * 4)   // 102400

// ---------------------------------------------------------------------------
// Scratch (static device globals)
// ---------------------------------------------------------------------------
__device__ float g_specT[(size_t)NCOL * KTOT];      // spec m-major [m][k], fp32
__device__ float g_frames[(size_t)NCOL * NFFT];     // frames [m][n]
__device__ float g_xr[(size_t)BATCH * DIM * SEQL];  // tf32-rounded x (k-major)
__device__ float g_Wp[(size_t)DIM * MPERM];         // permuted W, k-major, tf32
__device__ float2 g_tw[1024];                       // exp(+2*pi*i*a/1024)
__device__ float  g_winS[NFFT];                     // hann[n] / 1024

__device__ __forceinline__ float to_tf32(float x) {
    uint32_t y;
    asm("cvt.rna.tf32.f32 %0, %1;" : "=r"(y) : "f"(x));
    return __uint_as_float(y);
}

__device__ __forceinline__ void mma_tf32(float c[4], const uint32_t a[4], const uint32_t b[2]) {
    asm volatile(
        "mma.sync.aligned.m16n8k8.row.col.f32.tf32.tf32.f32 "
        "{%0,%1,%2,%3}, {%4,%5,%6,%7}, {%8,%9}, {%0,%1,%2,%3};\n"
        : "+f"(c[0]), "+f"(c[1]), "+f"(c[2]), "+f"(c[3])
        : "r"(a[0]), "r"(a[1]), "r"(a[2]), "r"(a[3]), "r"(b[0]), "r"(b[1]));
}

#define CP_ASYNC_CG(dst_u32, src_ptr) \
    asm volatile("cp.async.cg.shared.global [%0], [%1], 16;\n" \
                 :: "r"(dst_u32), "l"(src_ptr))
#define CP_COMMIT() asm volatile("cp.async.commit_group;\n")
#define CP_WAIT1()  asm volatile("cp.async.wait_group 1;\n")
#define CP_WAIT0()  asm volatile("cp.async.wait_group 0;\n")

// ---------------------------------------------------------------------------
// Prep kernels
// ---------------------------------------------------------------------------
// Twiddle table exp(+2*pi*i*a/1024) (full 1024) + scaled hann window.
__global__ void gen_tables_kernel() {
    int i = blockIdx.x * blockDim.x + threadIdx.x;
    if (i < 1024) {
        float s, c;
        sincosf(TWO_PI * (float)i * (1.0f / 1024.0f), &s, &c);
        g_tw[i] = make_float2(c, s);
        float w = 0.5f * (1.0f - c);      // hann[i] = 0.5*(1-cos(2*pi*i/1024))
        g_winS[i] = w * (1.0f / 1024.0f);
    }
}

// Permute + transpose + tf32-round W into g_Wp[k][m'] (k-major).
__global__ void wperm_kernel(const float* __restrict__ W) {
    int idx = blockIdx.x * blockDim.x + threadIdx.x;
    if (idx >= DIM * MPERM) return;
    int k = idx / MPERM;
    int mp = idx - k * MPERM;
    int tile = mp >> 4, w = mp & 15;
    int bin = tile * 8 + (w & 7);
    float val = 0.0f;
    if (bin < FBINS) {
        int o = (w < 8) ? bin : (FBINS + bin);
        val = to_tf32(W[(size_t)o * DIM + k]);
    }
    g_Wp[idx] = val;
}

// tf32-round x (vectorized, layout unchanged)
__global__ void xround_kernel(const float* __restrict__ x) {
    int idx = blockIdx.x * blockDim.x + threadIdx.x;
    if (idx >= BATCH * DIM * SEQL / 4) return;
    float4 v = ((const float4*)x)[idx];
    v.x = to_tf32(v.x); v.y = to_tf32(v.y);
    v.z = to_tf32(v.z); v.w = to_tf32(v.w);
    ((float4*)g_xr)[idx] = v;
}

// ---------------------------------------------------------------------------
// GEMM1 (TF32 mma.sync, cp.async double-buffered, fused spectrum epilogue):
//   h[m'][n] = sum_k Wp[k][m'] * xr[b][k][l]
//   512 threads, 16 warps (2 m x 8 n), warp tile 64x32, acc 64 regs/thread.
// ---------------------------------------------------------------------------
__global__ __launch_bounds__(NTHR, 1)
void gemm1_mma(const float* __restrict__ bias) {
    extern __shared__ float sm[];
    const uint32_t smem_u32 = (uint32_t)__cvta_generic_to_shared(sm);

    const int m0 = blockIdx.x * BM;
    const int n0 = blockIdx.y * BN;
    const int bidx = n0 >> 12;
    const int l0 = n0 & (SEQL - 1);
    const float* xb = g_xr + (size_t)bidx * DIM * SEQL + l0;

    const int tid = threadIdx.x;
    const int wid = tid >> 5, lane = tid & 31;
    const int wm = (wid & 1) * 64, wn = (wid >> 1) * 32;
    const int lr = lane >> 2, lc = lane & 3;

    float acc[4][4][4];
#pragma unroll
    for (int i = 0; i < 4; i++)
#pragma unroll
        for (int j = 0; j < 4; j++)
#pragma unroll
            for (int q = 0; q < 4; q++) acc[i][j][q] = 0.0f;

    const int T = DIM / BK;   // 16

    auto load_stage = [&](int s) {
        const int k0 = s * BK;
        const uint32_t a_base = smem_u32 + (s & 1) * (STAGE_WORDS * 4);
        const uint32_t b_base = a_base + A_WORDS * 4;
#pragma unroll
        for (int i = 0; i < 2; i++) {              // A: 32 rows x 32 float4
            int ch = tid + NTHR * i;
            int r = ch >> 5, c16 = ch & 31;
            CP_ASYNC_CG(a_base + (r * ASTRIDE + c16 * 4) * 4,
                        g_Wp + (size_t)(k0 + r) * MPERM + m0 + c16 * 4);
        }
#pragma unroll
        for (int i = 0; i < 4; i++) {              // B: 32 rows x 64 float4
            int ch = tid + NTHR * i;
            int r = ch >> 6, c16 = ch & 63;
            CP_ASYNC_CG(b_base + (r * BSTRIDE + c16 * 4) * 4,
                        xb + (size_t)(k0 + r) * SEQL + c16 * 4);
        }
        CP_COMMIT();
    };

    load_stage(0);
    for (int s = 0; s < T; s++) {
        if (s + 1 < T) { load_stage(s + 1); CP_WAIT1(); } else { CP_WAIT0(); }
        __syncthreads();
        const float* As = sm + (s & 1) * STAGE_WORDS;
        const float* Bs = As + A_WORDS;
#pragma unroll
        for (int k8 = 0; k8 < BK; k8 += 8) {
            uint32_t af[4][4], bf[4][2];
#pragma unroll
            for (int im = 0; im < 4; im++) {
                int rm = wm + im * 16 + lr;
                af[im][0] = __float_as_uint(As[(k8 + lc) * ASTRIDE + rm]);
                af[im][1] = __float_as_uint(As[(k8 + lc) * ASTRIDE + rm + 8]);
                af[im][2] = __float_as_uint(As[(k8 + 4 + lc) * ASTRIDE + rm]);
                af[im][3] = __float_as_uint(As[(k8 + 4 + lc) * ASTRIDE + rm + 8]);
            }
#pragma unroll
            for (int jn = 0; jn < 4; jn++) {
                int cb = wn + jn * 8 + lr;
                bf[jn][0] = __float_as_uint(Bs[(k8 + lc) * BSTRIDE + cb]);
                bf[jn][1] = __float_as_uint(Bs[(k8 + 4 + lc) * BSTRIDE + cb]);
            }
#pragma unroll
            for (int im = 0; im < 4; im++)
#pragma unroll
                for (int jn = 0; jn < 4; jn++)
                    mma_tf32(acc[im][jn], af[im], bf[jn]);
        }
        __syncthreads();
    }

    // ---- Fused spectrum epilogue, transposed to spec_T[m][k] ----
    const int TS = 136;
    float* Tt = sm;                        // 128 x 136 floats (69.6KB < 102.4KB)
    const int bin0 = blockIdx.x * 64;
    int width = FBINS - bin0; if (width > 64) width = 64; if (width < 0) width = 0;

    for (int h = 0; h < 2; h++) {
        if ((wid >> 3) == h) {             // warps covering n-cols [128h, 128h+128)
            int cbase = wn & 127;
#pragma unroll
            for (int im = 0; im < 4; im++) {
                int bin_l = ((wid & 1) * 4 + im) * 8 + lr;   // 0..63
                int bin = bin0 + bin_l;
                float bmag = (bin < FBINS) ? bias[bin] : 0.0f;
                float bph  = (bin < FBINS) ? bias[FBINS + bin] : 0.0f;
#pragma unroll
                for (int jn = 0; jn < 4; jn++) {
                    int c_l = cbase + jn * 8 + 2 * lc;
                    float m0v = fminf(expf(acc[im][jn][0] + bmag), 100.0f);
                    float m1v = fminf(expf(acc[im][jn][1] + bmag), 100.0f);
                    float s0, c0, s1, c1;
                    sincosf(acc[im][jn][2] + bph, &s0, &c0);
                    sincosf(acc[im][jn][3] + bph, &s1, &c1);
                    Tt[c_l * TS + bin_l]            = m0v * c0;
                    Tt[(c_l + 1) * TS + bin_l]      = m1v * c1;
                    Tt[c_l * TS + 64 + bin_l]       = m0v * s0;
                    Tt[(c_l + 1) * TS + 64 + bin_l] = m1v * s1;
                }
            }
        }
        __syncthreads();
        for (int sidx = wid; sidx < 256; sidx += 16) {
            int c_l = sidx >> 1, part = sidx & 1;
            int m_glob = n0 + h * 128 + c_l;
            float* dst = g_specT + (size_t)m_glob * KTOT + (part ? (KR + bin0) : bin0);
            const float* src = Tt + c_l * TS + part * 64;
            if (lane < width)      dst[lane]      = src[lane];
            if (lane + 32 < width) dst[lane + 32] = src[lane + 32];
        }
        __syncthreads();
    }
}

// ---------------------------------------------------------------------------
// Per-frame 1024-point inverse FFT, radix-4 Stockham (output-scatter), 5 stages.
//   Stage t (s = 4^t), butterfly i in 0..255:
//     a=X[i], b=X[i+256], c=X[i+512], d=X[i+768]
//     t0=a+c t1=a-c t2=b+d t3=+i*(b-d)
//     o = (i & (s-1)) + ((i >> 2t) << (2t+2));  ps = i & ~(s-1)
//     Y[o]=t0+t2; Y[o+s]=(t1+t3)*W^ps; Y[o+2s]=(t0-t2)*W^2ps; Y[o+3s]=(t1-t3)*W^3ps
//   (W = exp(+2*pi*i/1024); derived by composing two verified radix-2 stages)
// ---------------------------------------------------------------------------
__device__ __forceinline__ float2 cmul(float2 x, float2 w) {
    return make_float2(x.x * w.x - x.y * w.y, x.x * w.y + x.y * w.x);
}

__global__ __launch_bounds__(256)
void ifft4_kernel() {
    __shared__ float2 bufA[1024];
    __shared__ float2 bufB[1024];
    const int m = blockIdx.x;
    const int tid = threadIdx.x;
    const float* src = g_specT + (size_t)m * KTOT;

    // Load + Hermitian extension
#pragma unroll
    for (int h = 0; h < 2; h++) {
        int j = tid + h * 256;                 // 0..511
        float re = src[j];
        float im = src[KR + j];
        bufA[j] = make_float2(re, im);
        if (j > 0) bufA[1024 - j] = make_float2(re, -im);
    }
    if (tid == 0)
        bufA[512] = make_float2(src[512], src[KR + 512]);
    __syncthreads();

    float2* X = bufA;
    float2* Y = bufB;
#pragma unroll
    for (int st = 0; st < 5; st++) {
        const int s = 1 << (2 * st);
        const int i = tid;
        float2 a = X[i];
        float2 b = X[i + 256];
        float2 c = X[i + 512];
        float2 d = X[i + 768];
        float2 t0 = make_float2(a.x + c.x, a.y + c.y);
        float2 t1 = make_float2(a.x - c.x, a.y - c.y);
        float2 t2 = make_float2(b.x + d.x, b.y + d.y);
        float2 t3 = make_float2(-(b.y - d.y), b.x - d.x);   // +i*(b-d)
        int ps = i & ~(s - 1);
        int o  = (i & (s - 1)) + ((i >> (2 * st)) << (2 * st + 2));
        float2 F0 = make_float2(t0.x + t2.x, t0.y + t2.y);
        float2 F1 = make_float2(t1.x + t3.x, t1.y + t3.y);
        float2 F2 = make_float2(t0.x - t2.x, t0.y - t2.y);
        float2 F3 = make_float2(t1.x - t3.x, t1.y - t3.y);
        Y[o]         = F0;
        Y[o + s]     = cmul(F1, g_tw[ps]);
        Y[o + 2 * s] = cmul(F2, g_tw[2 * ps]);
        Y[o + 3 * s] = cmul(F3, g_tw[3 * ps]);
        __syncthreads();
        float2* t = X; X = Y; Y = t;
    }
    // 5 swaps -> result in bufB (== X), natural order
    float* dst = g_frames + (size_t)m * NFFT;
#pragma unroll
    for (int h = 0; h < 4; h++) {
        int n = tid + h * 256;
        dst[n] = X[n].x * g_winS[n];
    }
}

// ---------------------------------------------------------------------------
// Overlap-add gather + analytic window-square envelope + center trim.
// ---------------------------------------------------------------------------
__global__ void ola_kernel(float* __restrict__ out) {
    int idx = blockIdx.x * blockDim.x + threadIdx.x;
    if (idx >= BATCH * OUTPER) return;
    int b = idx >> 20;
    int t = idx & (OUTPER - 1);
    int g = t + PAD;
    int lmin = (g - (NFFT - 1) + (HOP - 1)) >> 8;
    if (lmin < 0) lmin = 0;
    int lmax = g >> 8;
    if (lmax > SEQL - 1) lmax = SEQL - 1;

    const float* fb = g_frames + (size_t)b * SEQL * NFFT;
    float acc = 0.0f, env = 0.0f;
    const float inv = 1.0f / (float)NFFT;
    for (int l = lmin; l <= lmax; ++l) {
        int n = g - (l << 8);
        float w = 0.5f * (1.0f - cosf(TWO_PI * (float)n * inv));
        acc += fb[(size_t)l * NFFT + n];
        env += w * w;
    }
    out[idx] = acc / (env > 1e-11f ? env : 1.0f);
}

// ---------------------------------------------------------------------------
// Launch
// ---------------------------------------------------------------------------
extern "C" void kernel_launch(void* const* d_in, const int* in_sizes, int n_in,
                              void* d_out, int out_size) {
    const float* x    = (const float*)d_in[0];   // (16, 512, 4096)
    const float* W    = (const float*)d_in[1];   // (1026, 512)
    const float* bias = (const float*)d_in[2];   // (1026,)
    float* out = (float*)d_out;                  // (16, 1048576)

    cudaFuncSetAttribute(gemm1_mma, cudaFuncAttributeMaxDynamicSharedMemorySize, SMEM_BYTES);

    gen_tables_kernel<<<4, 256>>>();
    wperm_kernel<<<(DIM * MPERM + 255) / 256, 256>>>(W);
    xround_kernel<<<(BATCH * DIM * SEQL / 4 + 255) / 256, 256>>>(x);

    gemm1_mma<<<dim3(MPERM / BM, NCOL / BN), NTHR, SMEM_BYTES>>>(bias);

    ifft4_kernel<<<NCOL, 256>>>();

    ola_kernel<<<(BATCH * OUTPER + 255) / 256, 256>>>(out);
}

// round 10
// speedup vs baseline: 4.9072x; 1.0158x over previous
#include <cuda_runtime.h>
#include <cuda_bf16.h>
#include <cstdint>
#include <math.h>

// Problem constants
#define BATCH   16
#define DIM     512
#define SEQL    4096
#define NFFT    1024
#define HOP     256
#define FBINS   513          // NFFT/2 + 1
#define NCOL    65536        // BATCH * SEQL
#define OUTPER  1048576      // SEQL * HOP
#define PAD     384          // (NFFT - HOP)/2
#define TWO_PI  6.283185307179586476925286766559f

// spec_T K layout: [Re: 0..512][pad][Im: 544..1056][pad]
#define KR      544
#define KTOT    1088

// Permuted-W logical M: tiles of 16 rows = {8 mag bins, same 8 phase bins}
#define MPERM   1152
#define NMBLK   9            // MPERM / 128

// GEMM1 tiling: block 128x256, 512 threads, warp tile 64x32 (2x8 grid)
#define BM 128
#define BN 256
#define BK 32
#define NTHR 512
// Fragment-major smem: A tile 4 k8-groups x 8 mtile16 atoms x 128 floats = 4096
//                      B tile 4 k8-groups x 32 ntile8 atoms x 64 floats = 8192
#define A_WORDS 4096
#define B_WORDS 8192
#define STAGE_WORDS (A_WORDS + B_WORDS)    // 12288
#define SMEM_BYTES (2 * STAGE_WORDS * 4)   // 98304

// ---------------------------------------------------------------------------
// Scratch (static device globals)
// ---------------------------------------------------------------------------
__device__ float g_specT[(size_t)NCOL * KTOT];      // spec m-major [m][k], fp32
__device__ float g_frames[(size_t)NCOL * NFFT];     // frames [m][n]
__device__ float g_xB[(size_t)BATCH * DIM * SEQL];  // x, fragment-major, tf32
__device__ float g_Wp[(size_t)16 * NMBLK * A_WORDS];// W, fragment-major, tf32
__device__ float2 g_tw[1024];                       // exp(+2*pi*i*a/1024)
__device__ float  g_winS[NFFT];                     // hann[n] / 1024

__device__ __forceinline__ float to_tf32(float x) {
    uint32_t y;
    asm("cvt.rna.tf32.f32 %0, %1;" : "=r"(y) : "f"(x));
    return __uint_as_float(y);
}

__device__ __forceinline__ void mma_tf32(float c[4], const uint32_t a[4], const uint32_t b[2]) {
    asm volatile(
        "mma.sync.aligned.m16n8k8.row.col.f32.tf32.tf32.f32 "
        "{%0,%1,%2,%3}, {%4,%5,%6,%7}, {%8,%9}, {%0,%1,%2,%3};\n"
        : "+f"(c[0]), "+f"(c[1]), "+f"(c[2]), "+f"(c[3])
        : "r"(a[0]), "r"(a[1]), "r"(a[2]), "r"(a[3]), "r"(b[0]), "r"(b[1]));
}

#define CP_ASYNC_CG(dst_u32, src_ptr) \
    asm volatile("cp.async.cg.shared.global [%0], [%1], 16;\n" \
                 :: "r"(dst_u32), "l"(src_ptr))
#define CP_COMMIT() asm volatile("cp.async.commit_group;\n")
#define CP_WAIT1()  asm volatile("cp.async.wait_group 1;\n")
#define CP_WAIT0()  asm volatile("cp.async.wait_group 0;\n")

// ---------------------------------------------------------------------------
// Prep kernels
// ---------------------------------------------------------------------------
// Twiddle table exp(+2*pi*i*a/1024) (full 1024) + scaled hann window.
__global__ void gen_tables_kernel() {
    int i = blockIdx.x * blockDim.x + threadIdx.x;
    if (i < 1024) {
        float s, c;
        sincosf(TWO_PI * (float)i * (1.0f / 1024.0f), &s, &c);
        g_tw[i] = make_float2(c, s);
        float w = 0.5f * (1.0f - c);      // hann[i] = 0.5*(1-cos(2*pi*i/1024))
        g_winS[i] = w * (1.0f / 1024.0f);
    }
}

// W -> fragment-major g_Wp[kchunk][mblock][k8idx][mtile][lane][4] (tf32).
// value[lane][q]: k = kchunk*32 + k8idx*8 + (q>=2)*4 + lc,
//                 m' = mblock*128 + mtile*16 + lr + (q&1)*8
// m' -> {mag,phase} permutation: tile=m'>>4, w=m'&15, bin=tile*8+(w&7),
//                                W-row = (w<8)? bin : FBINS+bin
__global__ void wperm_kernel(const float* __restrict__ W) {
    int i = blockIdx.x * blockDim.x + threadIdx.x;
    if (i >= 16 * NMBLK * A_WORDS) return;
    int qq    = i & 3;
    int lane  = (i >> 2) & 31;
    int mtile = (i >> 7) & 7;
    int k8idx = (i >> 10) & 3;
    int rest  = i >> 12;
    int mblock = rest % NMBLK;
    int kchunk = rest / NMBLK;
    int lr = lane >> 2, lc = lane & 3;
    int k  = kchunk * 32 + k8idx * 8 + ((qq >> 1) << 2) + lc;
    int mp = mblock * 128 + mtile * 16 + lr + ((qq & 1) << 3);
    int tile = mp >> 4, w = mp & 15;
    int bin = tile * 8 + (w & 7);
    float val = 0.0f;
    if (bin < FBINS) {
        int o = (w < 8) ? bin : (FBINS + bin);
        val = to_tf32(W[(size_t)o * DIM + k]);
    }
    g_Wp[i] = val;
}

// x -> fragment-major g_xB[b][kchunk][lblock][k8idx][ltile][lane][2] (tf32).
// value[lane][q]: k = kchunk*32 + k8idx*8 + q*4 + lc, l = lblock*256 + ltile*8 + lr
__global__ void xpermute_kernel(const float* __restrict__ x) {
    int j = blockIdx.x * blockDim.x + threadIdx.x;   // pair index
    if (j >= BATCH * DIM * SEQL / 2) return;
    int lane  = j & 31;
    int ltile = (j >> 5) & 31;
    int k8idx = (j >> 10) & 3;
    int lblock = (j >> 12) & 15;
    int kchunk = (j >> 16) & 15;
    int b = j >> 20;
    int lr = lane >> 2, lc = lane & 3;
    int k = kchunk * 32 + k8idx * 8 + lc;
    int l = lblock * 256 + ltile * 8 + lr;
    const float* xb = x + (size_t)b * DIM * SEQL;
    float v0 = to_tf32(xb[(size_t)k * SEQL + l]);
    float v1 = to_tf32(xb[(size_t)(k + 4) * SEQL + l]);
    ((float2*)g_xB)[j] = make_float2(v0, v1);
}

// ---------------------------------------------------------------------------
// GEMM1 (TF32 mma.sync, cp.async double-buffered, fragment-major operands,
// fused spectrum epilogue writing spec_T[m][k]):
//   512 threads, 16 warps (2 m x 8 n), warp tile 64x32, acc 64 regs/thread.
// ---------------------------------------------------------------------------
__global__ __launch_bounds__(NTHR, 1)
void gemm1_mma(const float* __restrict__ bias) {
    extern __shared__ float sm[];
    const uint32_t smem_u32 = (uint32_t)__cvta_generic_to_shared(sm);

    const int mblock = blockIdx.x;
    const int n0 = blockIdx.y * BN;
    const int bidx = n0 >> 12;
    const int lblock = (n0 & (SEQL - 1)) >> 8;

    const int tid = threadIdx.x;
    const int wid = tid >> 5, lane = tid & 31;
    const int wn = (wid >> 1) * 32;
    const int lr = lane >> 2, lc = lane & 3;

    float acc[4][4][4];
#pragma unroll
    for (int i = 0; i < 4; i++)
#pragma unroll
        for (int j = 0; j < 4; j++)
#pragma unroll
            for (int q = 0; q < 4; q++) acc[i][j][q] = 0.0f;

    const int T = DIM / BK;   // 16 kchunks

    auto load_stage = [&](int s) {
        const uint32_t a_base = smem_u32 + (s & 1) * (STAGE_WORDS * 4);
        const uint32_t b_base = a_base + A_WORDS * 4;
        const float* asrc = g_Wp + ((size_t)s * NMBLK + mblock) * A_WORDS;
        const float* bsrc = g_xB + ((size_t)bidx * 16 * 16 + (size_t)s * 16 + lblock) * B_WORDS;
#pragma unroll
        for (int i = 0; i < 2; i++) {              // A: 1024 float4, linear
            int ch = tid + NTHR * i;
            CP_ASYNC_CG(a_base + ch * 16, asrc + ch * 4);
        }
#pragma unroll
        for (int i = 0; i < 4; i++) {              // B: 2048 float4, linear
            int ch = tid + NTHR * i;
            CP_ASYNC_CG(b_base + ch * 16, bsrc + ch * 4);
        }
        CP_COMMIT();
    };

    // per-warp fragment base offsets (floats)
    const int a_off = (wid & 1) * 4 * 128 + lane * 4;    // + mtile*... via im*128? see below
    const int b_off = (wid >> 1) * 4 * 64 + lane * 2;

    load_stage(0);
    for (int s = 0; s < T; s++) {
        if (s + 1 < T) { load_stage(s + 1); CP_WAIT1(); } else { CP_WAIT0(); }
        __syncthreads();
        const float* As = sm + (s & 1) * STAGE_WORDS;
        const float* Bs = As + A_WORDS;
#pragma unroll
        for (int k8i = 0; k8i < 4; k8i++) {
            const float* Ak = As + k8i * 1024 + a_off;   // [mtile][lane][4]
            const float* Bk = Bs + k8i * 2048 + b_off;   // [ntile][lane][2]
            uint32_t af[4][4], bf[4][2];
#pragma unroll
            for (int im = 0; im < 4; im++) {
                float4 v = *(const float4*)(Ak + im * 128);
                af[im][0] = __float_as_uint(v.x);
                af[im][1] = __float_as_uint(v.y);
                af[im][2] = __float_as_uint(v.z);
                af[im][3] = __float_as_uint(v.w);
            }
#pragma unroll
            for (int jn = 0; jn < 4; jn++) {
                float2 v = *(const float2*)(Bk + jn * 64);
                bf[jn][0] = __float_as_uint(v.x);
                bf[jn][1] = __float_as_uint(v.y);
            }
#pragma unroll
            for (int im = 0; im < 4; im++)
#pragma unroll
                for (int jn = 0; jn < 4; jn++)
                    mma_tf32(acc[im][jn], af[im], bf[jn]);
        }
        __syncthreads();
    }

    // ---- Fused spectrum epilogue, transposed to spec_T[m][k] ----
    const int TS = 136;
    float* Tt = sm;                        // 128 x 136 floats (69.6KB < 96KB)
    const int bin0 = mblock * 64;
    int width = FBINS - bin0; if (width > 64) width = 64; if (width < 0) width = 0;

    for (int h = 0; h < 2; h++) {
        if ((wid >> 3) == h) {             // warps covering n-cols [128h, 128h+128)
            int cbase = wn & 127;
#pragma unroll
            for (int im = 0; im < 4; im++) {
                int bin_l = ((wid & 1) * 4 + im) * 8 + lr;   // 0..63
                int bin = bin0 + bin_l;
                float bmag = (bin < FBINS) ? bias[bin] : 0.0f;
                float bph  = (bin < FBINS) ? bias[FBINS + bin] : 0.0f;
#pragma unroll
                for (int jn = 0; jn < 4; jn++) {
                    int c_l = cbase + jn * 8 + 2 * lc;
                    float m0v = fminf(expf(acc[im][jn][0] + bmag), 100.0f);
                    float m1v = fminf(expf(acc[im][jn][1] + bmag), 100.0f);
                    float s0, c0, s1, c1;
                    sincosf(acc[im][jn][2] + bph, &s0, &c0);
                    sincosf(acc[im][jn][3] + bph, &s1, &c1);
                    Tt[c_l * TS + bin_l]            = m0v * c0;
                    Tt[(c_l + 1) * TS + bin_l]      = m1v * c1;
                    Tt[c_l * TS + 64 + bin_l]       = m0v * s0;
                    Tt[(c_l + 1) * TS + 64 + bin_l] = m1v * s1;
                }
            }
        }
        __syncthreads();
        for (int sidx = wid; sidx < 256; sidx += 16) {
            int c_l = sidx >> 1, part = sidx & 1;
            int m_glob = n0 + h * 128 + c_l;
            float* dst = g_specT + (size_t)m_glob * KTOT + (part ? (KR + bin0) : bin0);
            const float* src = Tt + c_l * TS + part * 64;
            if (lane < width)      dst[lane]      = src[lane];
            if (lane + 32 < width) dst[lane + 32] = src[lane + 32];
        }
        __syncthreads();
    }
}

// ---------------------------------------------------------------------------
// Per-frame 1024-point inverse FFT, radix-4 Stockham (output-scatter), 5 stages.
// ---------------------------------------------------------------------------
__device__ __forceinline__ float2 cmul(float2 x, float2 w) {
    return make_float2(x.x * w.x - x.y * w.y, x.x * w.y + x.y * w.x);
}

__global__ __launch_bounds__(256)
void ifft4_kernel() {
    __shared__ float2 bufA[1024];
    __shared__ float2 bufB[1024];
    const int m = blockIdx.x;
    const int tid = threadIdx.x;
    const float* src = g_specT + (size_t)m * KTOT;

    // Load + Hermitian extension
#pragma unroll
    for (int h = 0; h < 2; h++) {
        int j = tid + h * 256;                 // 0..511
        float re = src[j];
        float im = src[KR + j];
        bufA[j] = make_float2(re, im);
        if (j > 0) bufA[1024 - j] = make_float2(re, -im);
    }
    if (tid == 0)
        bufA[512] = make_float2(src[512], src[KR + 512]);
    __syncthreads();

    float2* X = bufA;
    float2* Y = bufB;
#pragma unroll
    for (int st = 0; st < 5; st++) {
        const int s = 1 << (2 * st);
        const int i = tid;
        float2 a = X[i];
        float2 b = X[i + 256];
        float2 c = X[i + 512];
        float2 d = X[i + 768];
        float2 t0 = make_float2(a.x + c.x, a.y + c.y);
        float2 t1 = make_float2(a.x - c.x, a.y - c.y);
        float2 t2 = make_float2(b.x + d.x, b.y + d.y);
        float2 t3 = make_float2(-(b.y - d.y), b.x - d.x);   // +i*(b-d)
        int ps = i & ~(s - 1);
        int o  = (i & (s - 1)) + ((i >> (2 * st)) << (2 * st + 2));
        float2 F0 = make_float2(t0.x + t2.x, t0.y + t2.y);
        float2 F1 = make_float2(t1.x + t3.x, t1.y + t3.y);
        float2 F2 = make_float2(t0.x - t2.x, t0.y - t2.y);
        float2 F3 = make_float2(t1.x - t3.x, t1.y - t3.y);
        Y[o]         = F0;
        Y[o + s]     = cmul(F1, g_tw[ps]);
        Y[o + 2 * s] = cmul(F2, g_tw[2 * ps]);
        Y[o + 3 * s] = cmul(F3, g_tw[3 * ps]);
        __syncthreads();
        float2* t = X; X = Y; Y = t;
    }
    float* dst = g_frames + (size_t)m * NFFT;
#pragma unroll
    for (int h = 0; h < 4; h++) {
        int n = tid + h * 256;
        dst[n] = X[n].x * g_winS[n];
    }
}

// ---------------------------------------------------------------------------
// Overlap-add gather + analytic window-square envelope + center trim.
// ---------------------------------------------------------------------------
__global__ void ola_kernel(float* __restrict__ out) {
    int idx = blockIdx.x * blockDim.x + threadIdx.x;
    if (idx >= BATCH * OUTPER) return;
    int b = idx >> 20;
    int t = idx & (OUTPER - 1);
    int g = t + PAD;
    int lmin = (g - (NFFT - 1) + (HOP - 1)) >> 8;
    if (lmin < 0) lmin = 0;
    int lmax = g >> 8;
    if (lmax > SEQL - 1) lmax = SEQL - 1;

    const float* fb = g_frames + (size_t)b * SEQL * NFFT;
    float acc = 0.0f, env = 0.0f;
    const float inv = 1.0f / (float)NFFT;
    for (int l = lmin; l <= lmax; ++l) {
        int n = g - (l << 8);
        float w = 0.5f * (1.0f - cosf(TWO_PI * (float)n * inv));
        acc += fb[(size_t)l * NFFT + n];
        env += w * w;
    }
    out[idx] = acc / (env > 1e-11f ? env : 1.0f);
}

// ---------------------------------------------------------------------------
// Launch
// ---------------------------------------------------------------------------
extern "C" void kernel_launch(void* const* d_in, const int* in_sizes, int n_in,
                              void* d_out, int out_size) {
    const float* x    = (const float*)d_in[0];   // (16, 512, 4096)
    const float* W    = (const float*)d_in[1];   // (1026, 512)
    const float* bias = (const float*)d_in[2];   // (1026,)
    float* out = (float*)d_out;                  // (16, 1048576)

    cudaFuncSetAttribute(gemm1_mma, cudaFuncAttributeMaxDynamicSharedMemorySize, SMEM_BYTES);

    gen_tables_kernel<<<4, 256>>>();
    wperm_kernel<<<(16 * NMBLK * A_WORDS + 255) / 256, 256>>>(W);
    xpermute_kernel<<<(BATCH * DIM * SEQL / 2 + 255) / 256, 256>>>(x);

    gemm1_mma<<<dim3(NMBLK, NCOL / BN), NTHR, SMEM_BYTES>>>(bias);

    ifft4_kernel<<<NCOL, 256>>>();

    ola_kernel<<<(BATCH * OUTPER + 255) / 256, 256>>>(out);
}

// round 11
// speedup vs baseline: 5.5782x; 1.1367x over previous
#include <cuda_runtime.h>
#include <cuda_bf16.h>
#include <cstdint>
#include <math.h>

// Problem constants
#define BATCH   16
#define DIM     512
#define SEQL    4096
#define NFFT    1024
#define HOP     256
#define FBINS   513          // NFFT/2 + 1
#define NCOL    65536        // BATCH * SEQL
#define OUTPER  1048576      // SEQL * HOP
#define PAD     384          // (NFFT - HOP)/2
#define TWO_PI  6.283185307179586476925286766559f

// spec_T K layout: [Re: 0..512][pad][Im: 544..1056][pad]
#define KR      544
#define KTOT    1088

// GEMM1 covers bins 0..511 (8 mblocks); bin 512 handled by nyq_kernel.
#define NMBLK   8

// GEMM1 tiling: block 128x256, 512 threads, warp tile 64x32 (2x8 grid)
#define BM 128
#define BN 256
#define BK 32
#define NTHR 512
// Fragment-major smem: A tile 4 k8-groups x 8 mtile16 atoms x 128 floats = 4096
//                      B tile 4 k8-groups x 32 ntile8 atoms x 64 floats = 8192
#define A_WORDS 4096
#define B_WORDS 8192
#define STAGE_WORDS (A_WORDS + B_WORDS)    // 12288
#define SMEM_BYTES (2 * STAGE_WORDS * 4)   // 98304

// ---------------------------------------------------------------------------
// Scratch (static device globals)
// ---------------------------------------------------------------------------
__device__ float g_specT[(size_t)NCOL * KTOT];      // spec m-major [m][k], fp32
__device__ float g_frames[(size_t)NCOL * NFFT];     // frames [m][n]
__device__ float g_xB[(size_t)BATCH * DIM * SEQL];  // x, fragment-major, tf32
__device__ float g_Wp[(size_t)16 * NMBLK * A_WORDS];// W, fragment-major, tf32
__device__ float2 g_tw[1024];                       // exp(+2*pi*i*a/1024)
__device__ float  g_winS[NFFT];                     // hann[n] / 1024
__device__ float  g_invenv[OUTPER];                 // 1 / window-square envelope

__device__ __forceinline__ float to_tf32(float x) {
    uint32_t y;
    asm("cvt.rna.tf32.f32 %0, %1;" : "=r"(y) : "f"(x));
    return __uint_as_float(y);
}

__device__ __forceinline__ void mma_tf32(float c[4], const uint32_t a[4], const uint32_t b[2]) {
    asm volatile(
        "mma.sync.aligned.m16n8k8.row.col.f32.tf32.tf32.f32 "
        "{%0,%1,%2,%3}, {%4,%5,%6,%7}, {%8,%9}, {%0,%1,%2,%3};\n"
        : "+f"(c[0]), "+f"(c[1]), "+f"(c[2]), "+f"(c[3])
        : "r"(a[0]), "r"(a[1]), "r"(a[2]), "r"(a[3]), "r"(b[0]), "r"(b[1]));
}

#define CP_ASYNC_CG(dst_u32, src_ptr) \
    asm volatile("cp.async.cg.shared.global [%0], [%1], 16;\n" \
                 :: "r"(dst_u32), "l"(src_ptr))
#define CP_COMMIT() asm volatile("cp.async.commit_group;\n")
#define CP_WAIT1()  asm volatile("cp.async.wait_group 1;\n")
#define CP_WAIT0()  asm volatile("cp.async.wait_group 0;\n")

// ---------------------------------------------------------------------------
// Prep kernels
// ---------------------------------------------------------------------------
// Twiddle table exp(+2*pi*i*a/1024) (full 1024) + scaled hann window.
__global__ void gen_tables_kernel() {
    int i = blockIdx.x * blockDim.x + threadIdx.x;
    if (i < 1024) {
        float s, c;
        sincosf(TWO_PI * (float)i * (1.0f / 1024.0f), &s, &c);
        g_tw[i] = make_float2(c, s);
        float w = 0.5f * (1.0f - c);      // hann[i] = 0.5*(1-cos(2*pi*i/1024))
        g_winS[i] = w * (1.0f / 1024.0f);
    }
}

// Precompute 1/env(t): env = sum over valid frames of hann^2 (batch-independent).
__global__ void gen_invenv_kernel() {
    int t = blockIdx.x * blockDim.x + threadIdx.x;
    if (t >= OUTPER) return;
    int g = t + PAD;
    int lmin = (g - (NFFT - 1) + (HOP - 1)) >> 8;
    if (lmin < 0) lmin = 0;
    int lmax = g >> 8;
    if (lmax > SEQL - 1) lmax = SEQL - 1;
    float env = 0.0f;
    const float inv = 1.0f / (float)NFFT;
    for (int l = lmin; l <= lmax; ++l) {
        int n = g - (l << 8);
        float w = 0.5f * (1.0f - cosf(TWO_PI * (float)n * inv));
        env += w * w;
    }
    g_invenv[t] = 1.0f / (env > 1e-11f ? env : 1.0f);
}

// W -> fragment-major g_Wp[kchunk][mblock][k8idx][mtile][lane][4] (tf32).
__global__ void wperm_kernel(const float* __restrict__ W) {
    int i = blockIdx.x * blockDim.x + threadIdx.x;
    if (i >= 16 * NMBLK * A_WORDS) return;
    int qq    = i & 3;
    int lane  = (i >> 2) & 31;
    int mtile = (i >> 7) & 7;
    int k8idx = (i >> 10) & 3;
    int rest  = i >> 12;
    int mblock = rest % NMBLK;
    int kchunk = rest / NMBLK;
    int lr = lane >> 2, lc = lane & 3;
    int k  = kchunk * 32 + k8idx * 8 + ((qq >> 1) << 2) + lc;
    int mp = mblock * 128 + mtile * 16 + lr + ((qq & 1) << 3);
    int tile = mp >> 4, w = mp & 15;
    int bin = tile * 8 + (w & 7);                 // < 512 always (NMBLK=8)
    int o = (w < 8) ? bin : (FBINS + bin);
    g_Wp[i] = to_tf32(W[(size_t)o * DIM + k]);
}

// x -> fragment-major g_xB[b][kchunk][lblock][k8idx][ltile][lane][2] (tf32).
__global__ void xpermute_kernel(const float* __restrict__ x) {
    int j = blockIdx.x * blockDim.x + threadIdx.x;   // pair index
    if (j >= BATCH * DIM * SEQL / 2) return;
    int lane  = j & 31;
    int ltile = (j >> 5) & 31;
    int k8idx = (j >> 10) & 3;
    int lblock = (j >> 12) & 15;
    int kchunk = (j >> 16) & 15;
    int b = j >> 20;
    int lr = lane >> 2, lc = lane & 3;
    int k = kchunk * 32 + k8idx * 8 + lc;
    int l = lblock * 256 + ltile * 8 + lr;
    const float* xb = x + (size_t)b * DIM * SEQL;
    float v0 = to_tf32(xb[(size_t)k * SEQL + l]);
    float v1 = to_tf32(xb[(size_t)(k + 4) * SEQL + l]);
    ((float2*)g_xB)[j] = make_float2(v0, v1);
}

// Nyquist bin (512): plain fp32 dot products, fused spectrum.
__global__ __launch_bounds__(256)
void nyq_kernel(const float* __restrict__ x, const float* __restrict__ W,
                const float* __restrict__ bias) {
    __shared__ float wm[DIM], wp[DIM];
    int tid = threadIdx.x;
    for (int k = tid; k < DIM; k += 256) {
        wm[k] = W[(size_t)512 * DIM + k];
        wp[k] = W[(size_t)1025 * DIM + k];
    }
    __syncthreads();
    int n = blockIdx.x * 256 + tid;
    int b = n >> 12, l = n & (SEQL - 1);
    const float* xb = x + (size_t)b * DIM * SEQL + l;
    float am = 0.0f, ap = 0.0f;
#pragma unroll 8
    for (int k = 0; k < DIM; k++) {
        float xv = xb[(size_t)k * SEQL];
        am += wm[k] * xv;
        ap += wp[k] * xv;
    }
    float mag = fminf(__expf(am + bias[512]), 100.0f);
    float s, c;
    __sincosf(ap + bias[1025], &s, &c);
    g_specT[(size_t)n * KTOT + 512]      = mag * c;
    g_specT[(size_t)n * KTOT + KR + 512] = mag * s;
}

// ---------------------------------------------------------------------------
// GEMM1 (TF32 mma.sync, cp.async double-buffered, fragment-major operands,
// fused spectrum epilogue writing spec_T[m][k]): bins 0..511.
// ---------------------------------------------------------------------------
__global__ __launch_bounds__(NTHR, 1)
void gemm1_mma(const float* __restrict__ bias) {
    extern __shared__ float sm[];
    const uint32_t smem_u32 = (uint32_t)__cvta_generic_to_shared(sm);

    const int mblock = blockIdx.x;
    const int n0 = blockIdx.y * BN;
    const int bidx = n0 >> 12;
    const int lblock = (n0 & (SEQL - 1)) >> 8;

    const int tid = threadIdx.x;
    const int wid = tid >> 5, lane = tid & 31;
    const int wn = (wid >> 1) * 32;
    const int lr = lane >> 2, lc = lane & 3;

    float acc[4][4][4];
#pragma unroll
    for (int i = 0; i < 4; i++)
#pragma unroll
        for (int j = 0; j < 4; j++)
#pragma unroll
            for (int q = 0; q < 4; q++) acc[i][j][q] = 0.0f;

    const int T = DIM / BK;   // 16 kchunks

    auto load_stage = [&](int s) {
        const uint32_t a_base = smem_u32 + (s & 1) * (STAGE_WORDS * 4);
        const uint32_t b_base = a_base + A_WORDS * 4;
        const float* asrc = g_Wp + ((size_t)s * NMBLK + mblock) * A_WORDS;
        const float* bsrc = g_xB + ((size_t)bidx * 16 * 16 + (size_t)s * 16 + lblock) * B_WORDS;
#pragma unroll
        for (int i = 0; i < 2; i++) {              // A: 1024 float4, linear
            int ch = tid + NTHR * i;
            CP_ASYNC_CG(a_base + ch * 16, asrc + ch * 4);
        }
#pragma unroll
        for (int i = 0; i < 4; i++) {              // B: 2048 float4, linear
            int ch = tid + NTHR * i;
            CP_ASYNC_CG(b_base + ch * 16, bsrc + ch * 4);
        }
        CP_COMMIT();
    };

    const int a_off = (wid & 1) * 4 * 128 + lane * 4;
    const int b_off = (wid >> 1) * 4 * 64 + lane * 2;

    load_stage(0);
    for (int s = 0; s < T; s++) {
        if (s + 1 < T) { load_stage(s + 1); CP_WAIT1(); } else { CP_WAIT0(); }
        __syncthreads();
        const float* As = sm + (s & 1) * STAGE_WORDS;
        const float* Bs = As + A_WORDS;
#pragma unroll
        for (int k8i = 0; k8i < 4; k8i++) {
            const float* Ak = As + k8i * 1024 + a_off;   // [mtile][lane][4]
            const float* Bk = Bs + k8i * 2048 + b_off;   // [ntile][lane][2]
            uint32_t af[4][4], bf[4][2];
#pragma unroll
            for (int im = 0; im < 4; im++) {
                float4 v = *(const float4*)(Ak + im * 128);
                af[im][0] = __float_as_uint(v.x);
                af[im][1] = __float_as_uint(v.y);
                af[im][2] = __float_as_uint(v.z);
                af[im][3] = __float_as_uint(v.w);
            }
#pragma unroll
            for (int jn = 0; jn < 4; jn++) {
                float2 v = *(const float2*)(Bk + jn * 64);
                bf[jn][0] = __float_as_uint(v.x);
                bf[jn][1] = __float_as_uint(v.y);
            }
#pragma unroll
            for (int im = 0; im < 4; im++)
#pragma unroll
                for (int jn = 0; jn < 4; jn++)
                    mma_tf32(acc[im][jn], af[im], bf[jn]);
        }
        __syncthreads();
    }

    // ---- Fused spectrum epilogue, transposed to spec_T[m][k] ----
    // All 64 bins of this mblock are valid (< 512). Fast-math trig:
    // |phase| ~ O(1) and mag arg small -> __sincosf/__expf err ~5e-7,
    // 3 orders below the tf32 error floor.
    const int TS = 136;
    float* Tt = sm;                        // 128 x 136 floats (69.6KB < 96KB)
    const int bin0 = mblock * 64;

    for (int h = 0; h < 2; h++) {
        if ((wid >> 3) == h) {             // warps covering n-cols [128h, 128h+128)
            int cbase = wn & 127;
#pragma unroll
            for (int im = 0; im < 4; im++) {
                int bin_l = ((wid & 1) * 4 + im) * 8 + lr;   // 0..63
                int bin = bin0 + bin_l;
                float bmag = bias[bin];
                float bph  = bias[FBINS + bin];
#pragma unroll
                for (int jn = 0; jn < 4; jn++) {
                    int c_l = cbase + jn * 8 + 2 * lc;
                    float m0v = fminf(__expf(acc[im][jn][0] + bmag), 100.0f);
                    float m1v = fminf(__expf(acc[im][jn][1] + bmag), 100.0f);
                    float s0, c0, s1, c1;
                    __sincosf(acc[im][jn][2] + bph, &s0, &c0);
                    __sincosf(acc[im][jn][3] + bph, &s1, &c1);
                    Tt[c_l * TS + bin_l]            = m0v * c0;
                    Tt[(c_l + 1) * TS + bin_l]      = m1v * c1;
                    Tt[c_l * TS + 64 + bin_l]       = m0v * s0;
                    Tt[(c_l + 1) * TS + 64 + bin_l] = m1v * s1;
                }
            }
        }
        __syncthreads();
        for (int sidx = wid; sidx < 256; sidx += 16) {
            int c_l = sidx >> 1, part = sidx & 1;
            int m_glob = n0 + h * 128 + c_l;
            float* dst = g_specT + (size_t)m_glob * KTOT + (part ? (KR + bin0) : bin0);
            const float* src = Tt + c_l * TS + part * 64;
            dst[lane]      = src[lane];
            dst[lane + 32] = src[lane + 32];
        }
        __syncthreads();
    }
}

// ---------------------------------------------------------------------------
// Per-frame 1024-point inverse FFT, radix-4 Stockham (output-scatter), 5 stages.
// ---------------------------------------------------------------------------
__device__ __forceinline__ float2 cmul(float2 x, float2 w) {
    return make_float2(x.x * w.x - x.y * w.y, x.x * w.y + x.y * w.x);
}

__global__ __launch_bounds__(256)
void ifft4_kernel() {
    __shared__ float2 bufA[1024];
    __shared__ float2 bufB[1024];
    const int m = blockIdx.x;
    const int tid = threadIdx.x;
    const float* src = g_specT + (size_t)m * KTOT;

    // Load + Hermitian extension
#pragma unroll
    for (int h = 0; h < 2; h++) {
        int j = tid + h * 256;                 // 0..511
        float re = src[j];
        float im = src[KR + j];
        bufA[j] = make_float2(re, im);
        if (j > 0) bufA[1024 - j] = make_float2(re, -im);
    }
    if (tid == 0)
        bufA[512] = make_float2(src[512], src[KR + 512]);
    __syncthreads();

    float2* X = bufA;
    float2* Y = bufB;
#pragma unroll
    for (int st = 0; st < 5; st++) {
        const int s = 1 << (2 * st);
        const int i = tid;
        float2 a = X[i];
        float2 b = X[i + 256];
        float2 c = X[i + 512];
        float2 d = X[i + 768];
        float2 t0 = make_float2(a.x + c.x, a.y + c.y);
        float2 t1 = make_float2(a.x - c.x, a.y - c.y);
        float2 t2 = make_float2(b.x + d.x, b.y + d.y);
        float2 t3 = make_float2(-(b.y - d.y), b.x - d.x);   // +i*(b-d)
        int ps = i & ~(s - 1);
        int o  = (i & (s - 1)) + ((i >> (2 * st)) << (2 * st + 2));
        float2 F0 = make_float2(t0.x + t2.x, t0.y + t2.y);
        float2 F1 = make_float2(t1.x + t3.x, t1.y + t3.y);
        float2 F2 = make_float2(t0.x - t2.x, t0.y - t2.y);
        float2 F3 = make_float2(t1.x - t3.x, t1.y - t3.y);
        Y[o]         = F0;
        Y[o + s]     = cmul(F1, g_tw[ps]);
        Y[o + 2 * s] = cmul(F2, g_tw[2 * ps]);
        Y[o + 3 * s] = cmul(F3, g_tw[3 * ps]);
        __syncthreads();
        float2* t = X; X = Y; Y = t;
    }
    float* dst = g_frames + (size_t)m * NFFT;
#pragma unroll
    for (int h = 0; h < 4; h++) {
        int n = tid + h * 256;
        dst[n] = X[n].x * g_winS[n];
    }
}

// ---------------------------------------------------------------------------
// Overlap-add gather: 4 frame reads + precomputed inverse-envelope multiply.
// ---------------------------------------------------------------------------
__global__ void ola_kernel(float* __restrict__ out) {
    int idx = blockIdx.x * blockDim.x + threadIdx.x;
    if (idx >= BATCH * OUTPER) return;
    int b = idx >> 20;
    int t = idx & (OUTPER - 1);
    int g = t + PAD;
    int lmin = (g - (NFFT - 1) + (HOP - 1)) >> 8;
    if (lmin < 0) lmin = 0;
    int lmax = g >> 8;
    if (lmax > SEQL - 1) lmax = SEQL - 1;

    const float* fb = g_frames + (size_t)b * SEQL * NFFT;
    float acc = 0.0f;
    for (int l = lmin; l <= lmax; ++l)
        acc += fb[(size_t)l * NFFT + (g - (l << 8))];
    out[idx] = acc * g_invenv[t];
}

// ---------------------------------------------------------------------------
// Launch
// ---------------------------------------------------------------------------
extern "C" void kernel_launch(void* const* d_in, const int* in_sizes, int n_in,
                              void* d_out, int out_size) {
    const float* x    = (const float*)d_in[0];   // (16, 512, 4096)
    const float* W    = (const float*)d_in[1];   // (1026, 512)
    const float* bias = (const float*)d_in[2];   // (1026,)
    float* out = (float*)d_out;                  // (16, 1048576)

    cudaFuncSetAttribute(gemm1_mma, cudaFuncAttributeMaxDynamicSharedMemorySize, SMEM_BYTES);

    gen_tables_kernel<<<4, 256>>>();
    gen_invenv_kernel<<<OUTPER / 256, 256>>>();
    wperm_kernel<<<(16 * NMBLK * A_WORDS + 255) / 256, 256>>>(W);
    xpermute_kernel<<<(BATCH * DIM * SEQL / 2 + 255) / 256, 256>>>(x);

    nyq_kernel<<<NCOL / 256, 256>>>(x, W, bias);

    gemm1_mma<<<dim3(NMBLK, NCOL / BN), NTHR, SMEM_BYTES>>>(bias);

    ifft4_kernel<<<NCOL, 256>>>();

    ola_kernel<<<(BATCH * OUTPER + 255) / 256, 256>>>(out);
}

// round 12
// speedup vs baseline: 5.7062x; 1.0229x over previous
#include <cuda_runtime.h>
#include <cuda_bf16.h>
#include <cstdint>
#include <math.h>

// Problem constants
#define BATCH   16
#define DIM     512
#define SEQL    4096
#define NFFT    1024
#define HOP     256
#define FBINS   513          // NFFT/2 + 1
#define NCOL    65536        // BATCH * SEQL
#define OUTPER  1048576      // SEQL * HOP
#define PAD     384          // (NFFT - HOP)/2
#define TWO_PI  6.283185307179586476925286766559f

// spec_T K layout: [Re: 0..512][pad][Im: 544..1056][pad]
#define KR      544
#define KTOT    1088

// GEMM1 covers bins 0..511 (8 mblocks); bin 512 handled by nyq_kernel.
#define NMBLK   8

// GEMM1 tiling: block 128x256, 512 threads, warp tile 64x32 (2x8 grid)
#define BM 128
#define BN 256
#define BK 32
#define NTHR 512
#define A_WORDS 4096
#define B_WORDS 8192
#define STAGE_WORDS (A_WORDS + B_WORDS)    // 12288
#define SMEM_BYTES (2 * STAGE_WORDS * 4)   // 98304

// Fused iFFT+OLA: hops per block
#define HOPB 32

// ---------------------------------------------------------------------------
// Scratch (static device globals)
// ---------------------------------------------------------------------------
__device__ float g_specT[(size_t)NCOL * KTOT];      // spec m-major [m][k], fp32
__device__ float g_xB[(size_t)BATCH * DIM * SEQL];  // x, fragment-major, tf32
__device__ float g_Wp[(size_t)16 * NMBLK * A_WORDS];// W, fragment-major, tf32
__device__ float2 g_tw[1024];                       // exp(+2*pi*i*a/1024)
__device__ float  g_winS[NFFT];                     // hann[n] / 1024
__device__ float  g_invenv[OUTPER];                 // 1 / window-square envelope

__device__ __forceinline__ float to_tf32(float x) {
    uint32_t y;
    asm("cvt.rna.tf32.f32 %0, %1;" : "=r"(y) : "f"(x));
    return __uint_as_float(y);
}

__device__ __forceinline__ void mma_tf32(float c[4], const uint32_t a[4], const uint32_t b[2]) {
    asm volatile(
        "mma.sync.aligned.m16n8k8.row.col.f32.tf32.tf32.f32 "
        "{%0,%1,%2,%3}, {%4,%5,%6,%7}, {%8,%9}, {%0,%1,%2,%3};\n"
        : "+f"(c[0]), "+f"(c[1]), "+f"(c[2]), "+f"(c[3])
        : "r"(a[0]), "r"(a[1]), "r"(a[2]), "r"(a[3]), "r"(b[0]), "r"(b[1]));
}

#define CP_ASYNC_CG(dst_u32, src_ptr) \
    asm volatile("cp.async.cg.shared.global [%0], [%1], 16;\n" \
                 :: "r"(dst_u32), "l"(src_ptr))
#define CP_COMMIT() asm volatile("cp.async.commit_group;\n")
#define CP_WAIT1()  asm volatile("cp.async.wait_group 1;\n")
#define CP_WAIT0()  asm volatile("cp.async.wait_group 0;\n")

// ---------------------------------------------------------------------------
// Prep kernels
// ---------------------------------------------------------------------------
__global__ void gen_tables_kernel() {
    int i = blockIdx.x * blockDim.x + threadIdx.x;
    if (i < 1024) {
        float s, c;
        sincosf(TWO_PI * (float)i * (1.0f / 1024.0f), &s, &c);
        g_tw[i] = make_float2(c, s);
        float w = 0.5f * (1.0f - c);      // hann[i]
        g_winS[i] = w * (1.0f / 1024.0f);
    }
}

// Precompute 1/env(t): env = sum over valid frames of hann^2 (batch-independent).
__global__ void gen_invenv_kernel() {
    int t = blockIdx.x * blockDim.x + threadIdx.x;
    if (t >= OUTPER) return;
    int g = t + PAD;
    int lmin = (g - (NFFT - 1) + (HOP - 1)) >> 8;
    if (lmin < 0) lmin = 0;
    int lmax = g >> 8;
    if (lmax > SEQL - 1) lmax = SEQL - 1;
    float env = 0.0f;
    const float inv = 1.0f / (float)NFFT;
    for (int l = lmin; l <= lmax; ++l) {
        int n = g - (l << 8);
        float w = 0.5f * (1.0f - cosf(TWO_PI * (float)n * inv));
        env += w * w;
    }
    g_invenv[t] = 1.0f / (env > 1e-11f ? env : 1.0f);
}

// W -> fragment-major g_Wp[kchunk][mblock][k8idx][mtile][lane][4] (tf32).
__global__ void wperm_kernel(const float* __restrict__ W) {
    int i = blockIdx.x * blockDim.x + threadIdx.x;
    if (i >= 16 * NMBLK * A_WORDS) return;
    int qq    = i & 3;
    int lane  = (i >> 2) & 31;
    int mtile = (i >> 7) & 7;
    int k8idx = (i >> 10) & 3;
    int rest  = i >> 12;
    int mblock = rest % NMBLK;
    int kchunk = rest / NMBLK;
    int lr = lane >> 2, lc = lane & 3;
    int k  = kchunk * 32 + k8idx * 8 + ((qq >> 1) << 2) + lc;
    int mp = mblock * 128 + mtile * 16 + lr + ((qq & 1) << 3);
    int tile = mp >> 4, w = mp & 15;
    int bin = tile * 8 + (w & 7);                 // < 512 always (NMBLK=8)
    int o = (w < 8) ? bin : (FBINS + bin);
    g_Wp[i] = to_tf32(W[(size_t)o * DIM + k]);
}

// x -> fragment-major g_xB[b][kchunk][lblock][k8idx][ltile][lane][2] (tf32).
__global__ void xpermute_kernel(const float* __restrict__ x) {
    int j = blockIdx.x * blockDim.x + threadIdx.x;   // pair index
    if (j >= BATCH * DIM * SEQL / 2) return;
    int lane  = j & 31;
    int ltile = (j >> 5) & 31;
    int k8idx = (j >> 10) & 3;
    int lblock = (j >> 12) & 15;
    int kchunk = (j >> 16) & 15;
    int b = j >> 20;
    int lr = lane >> 2, lc = lane & 3;
    int k = kchunk * 32 + k8idx * 8 + lc;
    int l = lblock * 256 + ltile * 8 + lr;
    const float* xb = x + (size_t)b * DIM * SEQL;
    float v0 = to_tf32(xb[(size_t)k * SEQL + l]);
    float v1 = to_tf32(xb[(size_t)(k + 4) * SEQL + l]);
    ((float2*)g_xB)[j] = make_float2(v0, v1);
}

// Nyquist bin (512): plain fp32 dot products, fused spectrum.
__global__ __launch_bounds__(256)
void nyq_kernel(const float* __restrict__ x, const float* __restrict__ W,
                const float* __restrict__ bias) {
    __shared__ float wm[DIM], wp[DIM];
    int tid = threadIdx.x;
    for (int k = tid; k < DIM; k += 256) {
        wm[k] = W[(size_t)512 * DIM + k];
        wp[k] = W[(size_t)1025 * DIM + k];
    }
    __syncthreads();
    int n = blockIdx.x * 256 + tid;
    int b = n >> 12, l = n & (SEQL - 1);
    const float* xb = x + (size_t)b * DIM * SEQL + l;
    float am = 0.0f, ap = 0.0f;
#pragma unroll 8
    for (int k = 0; k < DIM; k++) {
        float xv = xb[(size_t)k * SEQL];
        am += wm[k] * xv;
        ap += wp[k] * xv;
    }
    float mag = fminf(__expf(am + bias[512]), 100.0f);
    float s, c;
    __sincosf(ap + bias[1025], &s, &c);
    g_specT[(size_t)n * KTOT + 512]      = mag * c;
    g_specT[(size_t)n * KTOT + KR + 512] = mag * s;
}

// ---------------------------------------------------------------------------
// GEMM1 (TF32 mma.sync, cp.async double-buffered, fragment-major operands,
// fused spectrum epilogue writing spec_T[m][k]): bins 0..511.
// ---------------------------------------------------------------------------
__global__ __launch_bounds__(NTHR, 1)
void gemm1_mma(const float* __restrict__ bias) {
    extern __shared__ float sm[];
    const uint32_t smem_u32 = (uint32_t)__cvta_generic_to_shared(sm);

    const int mblock = blockIdx.x;
    const int n0 = blockIdx.y * BN;
    const int bidx = n0 >> 12;
    const int lblock = (n0 & (SEQL - 1)) >> 8;

    const int tid = threadIdx.x;
    const int wid = tid >> 5, lane = tid & 31;
    const int wn = (wid >> 1) * 32;
    const int lr = lane >> 2, lc = lane & 3;

    float acc[4][4][4];
#pragma unroll
    for (int i = 0; i < 4; i++)
#pragma unroll
        for (int j = 0; j < 4; j++)
#pragma unroll
            for (int q = 0; q < 4; q++) acc[i][j][q] = 0.0f;

    const int T = DIM / BK;   // 16 kchunks

    auto load_stage = [&](int s) {
        const uint32_t a_base = smem_u32 + (s & 1) * (STAGE_WORDS * 4);
        const uint32_t b_base = a_base + A_WORDS * 4;
        const float* asrc = g_Wp + ((size_t)s * NMBLK + mblock) * A_WORDS;
        const float* bsrc = g_xB + ((size_t)bidx * 16 * 16 + (size_t)s * 16 + lblock) * B_WORDS;
#pragma unroll
        for (int i = 0; i < 2; i++) {
            int ch = tid + NTHR * i;
            CP_ASYNC_CG(a_base + ch * 16, asrc + ch * 4);
        }
#pragma unroll
        for (int i = 0; i < 4; i++) {
            int ch = tid + NTHR * i;
            CP_ASYNC_CG(b_base + ch * 16, bsrc + ch * 4);
        }
        CP_COMMIT();
    };

    const int a_off = (wid & 1) * 4 * 128 + lane * 4;
    const int b_off = (wid >> 1) * 4 * 64 + lane * 2;

    load_stage(0);
    for (int s = 0; s < T; s++) {
        if (s + 1 < T) { load_stage(s + 1); CP_WAIT1(); } else { CP_WAIT0(); }
        __syncthreads();
        const float* As = sm + (s & 1) * STAGE_WORDS;
        const float* Bs = As + A_WORDS;
#pragma unroll
        for (int k8i = 0; k8i < 4; k8i++) {
            const float* Ak = As + k8i * 1024 + a_off;
            const float* Bk = Bs + k8i * 2048 + b_off;
            uint32_t af[4][4], bf[4][2];
#pragma unroll
            for (int im = 0; im < 4; im++) {
                float4 v = *(const float4*)(Ak + im * 128);
                af[im][0] = __float_as_uint(v.x);
                af[im][1] = __float_as_uint(v.y);
                af[im][2] = __float_as_uint(v.z);
                af[im][3] = __float_as_uint(v.w);
            }
#pragma unroll
            for (int jn = 0; jn < 4; jn++) {
                float2 v = *(const float2*)(Bk + jn * 64);
                bf[jn][0] = __float_as_uint(v.x);
                bf[jn][1] = __float_as_uint(v.y);
            }
#pragma unroll
            for (int im = 0; im < 4; im++)
#pragma unroll
                for (int jn = 0; jn < 4; jn++)
                    mma_tf32(acc[im][jn], af[im], bf[jn]);
        }
        __syncthreads();
    }

    // ---- Fused spectrum epilogue, transposed to spec_T[m][k] ----
    const int TS = 136;
    float* Tt = sm;                        // 128 x 136 floats
    const int bin0 = mblock * 64;

    for (int h = 0; h < 2; h++) {
        if ((wid >> 3) == h) {
            int cbase = wn & 127;
#pragma unroll
            for (int im = 0; im < 4; im++) {
                int bin_l = ((wid & 1) * 4 + im) * 8 + lr;   // 0..63
                int bin = bin0 + bin_l;
                float bmag = bias[bin];
                float bph  = bias[FBINS + bin];
#pragma unroll
                for (int jn = 0; jn < 4; jn++) {
                    int c_l = cbase + jn * 8 + 2 * lc;
                    float m0v = fminf(__expf(acc[im][jn][0] + bmag), 100.0f);
                    float m1v = fminf(__expf(acc[im][jn][1] + bmag), 100.0f);
                    float s0, c0, s1, c1;
                    __sincosf(acc[im][jn][2] + bph, &s0, &c0);
                    __sincosf(acc[im][jn][3] + bph, &s1, &c1);
                    Tt[c_l * TS + bin_l]            = m0v * c0;
                    Tt[(c_l + 1) * TS + bin_l]      = m1v * c1;
                    Tt[c_l * TS + 64 + bin_l]       = m0v * s0;
                    Tt[(c_l + 1) * TS + 64 + bin_l] = m1v * s1;
                }
            }
        }
        __syncthreads();
        for (int sidx = wid; sidx < 256; sidx += 16) {
            int c_l = sidx >> 1, part = sidx & 1;
            int m_glob = n0 + h * 128 + c_l;
            float* dst = g_specT + (size_t)m_glob * KTOT + (part ? (KR + bin0) : bin0);
            const float* src = Tt + c_l * TS + part * 64;
            dst[lane]      = src[lane];
            dst[lane + 32] = src[lane + 32];
        }
        __syncthreads();
    }
}

// ---------------------------------------------------------------------------
// Fused iFFT + window + overlap-add. One block owns HOPB consecutive hops of
// one batch. It computes frames l = h0-2 .. h0+HOPB+1 sequentially (radix-4
// Stockham, 5 stages), keeps windowed frames in a 5-slot smem ring, and emits
// hop h (256 output samples) right after frame h+2 lands.
//   Output sample t (g=t+384): contributions from frames lp=h+d,
//   n = -d*256 + tid + 384;  in-range: d=-1,0,1 always; d=-2 iff tid<128;
//   d=+2 iff tid>=128. Out-of-range frames have zeroed ring slots (matches
//   the reference envelope, which excludes them).
// ---------------------------------------------------------------------------
__device__ __forceinline__ float2 cmul(float2 x, float2 w) {
    return make_float2(x.x * w.x - x.y * w.y, x.x * w.y + x.y * w.x);
}

__global__ __launch_bounds__(256)
void ifft_ola_kernel(float* __restrict__ out) {
    __shared__ float2 bufA[1024];
    __shared__ float2 bufB[1024];
    __shared__ float ring[5][1024];
    const int blk = blockIdx.x;
    const int b = blk / (SEQL / HOPB);
    const int h0 = (blk % (SEQL / HOPB)) * HOPB;
    const int tid = threadIdx.x;

    for (int l = h0 - 2; l <= h0 + HOPB + 1; ++l) {
        const int slot = (l + 10) % 5;
        if (l >= 0 && l < SEQL) {
            const float* src = g_specT + ((size_t)b * SEQL + l) * KTOT;
            // Load + Hermitian extension
#pragma unroll
            for (int h2 = 0; h2 < 2; h2++) {
                int j = tid + h2 * 256;               // 0..511
                float re = src[j];
                float im = src[KR + j];
                bufA[j] = make_float2(re, im);
                if (j > 0) bufA[1024 - j] = make_float2(re, -im);
            }
            if (tid == 0)
                bufA[512] = make_float2(src[512], src[KR + 512]);
            __syncthreads();

            float2* X = bufA;
            float2* Y = bufB;
#pragma unroll
            for (int st = 0; st < 5; st++) {
                const int s = 1 << (2 * st);
                const int i = tid;
                float2 a = X[i];
                float2 bb = X[i + 256];
                float2 c = X[i + 512];
                float2 d = X[i + 768];
                float2 t0 = make_float2(a.x + c.x, a.y + c.y);
                float2 t1 = make_float2(a.x - c.x, a.y - c.y);
                float2 t2 = make_float2(bb.x + d.x, bb.y + d.y);
                float2 t3 = make_float2(-(bb.y - d.y), bb.x - d.x);   // +i*(b-d)
                int ps = i & ~(s - 1);
                int o  = (i & (s - 1)) + ((i >> (2 * st)) << (2 * st + 2));
                float2 F0 = make_float2(t0.x + t2.x, t0.y + t2.y);
                float2 F1 = make_float2(t1.x + t3.x, t1.y + t3.y);
                float2 F2 = make_float2(t0.x - t2.x, t0.y - t2.y);
                float2 F3 = make_float2(t1.x - t3.x, t1.y - t3.y);
                Y[o]         = F0;
                Y[o + s]     = cmul(F1, g_tw[ps]);
                Y[o + 2 * s] = cmul(F2, g_tw[2 * ps]);
                Y[o + 3 * s] = cmul(F3, g_tw[3 * ps]);
                __syncthreads();
                float2* t = X; X = Y; Y = t;
            }
            // Window + store into ring slot
#pragma unroll
            for (int h2 = 0; h2 < 4; h2++) {
                int n = tid + h2 * 256;
                ring[slot][n] = X[n].x * g_winS[n];
            }
        } else {
#pragma unroll
            for (int h2 = 0; h2 < 4; h2++)
                ring[slot][tid + h2 * 256] = 0.0f;
        }
        __syncthreads();                     // ring slot visible to all

        const int h = l - 2;                 // hop emittable now
        if (h >= h0 && h < h0 + HOPB) {
            int t = h * HOP + tid;
            float acc = ring[(h - 1 + 10) % 5][640 + tid]
                      + ring[(h     + 10) % 5][384 + tid]
                      + ring[(h + 1 + 10) % 5][128 + tid];
            if (tid < 128)
                acc += ring[(h - 2 + 10) % 5][896 + tid];
            else
                acc += ring[(h + 2 + 10) % 5][tid - 128];
            out[(size_t)b * OUTPER + t] = acc * g_invenv[t];
        }
        __syncthreads();                     // emits done before slot reuse
    }
}

// ---------------------------------------------------------------------------
// Launch
// ---------------------------------------------------------------------------
extern "C" void kernel_launch(void* const* d_in, const int* in_sizes, int n_in,
                              void* d_out, int out_size) {
    const float* x    = (const float*)d_in[0];   // (16, 512, 4096)
    const float* W    = (const float*)d_in[1];   // (1026, 512)
    const float* bias = (const float*)d_in[2];   // (1026,)
    float* out = (float*)d_out;                  // (16, 1048576)

    cudaFuncSetAttribute(gemm1_mma, cudaFuncAttributeMaxDynamicSharedMemorySize, SMEM_BYTES);

    gen_tables_kernel<<<4, 256>>>();
    gen_invenv_kernel<<<OUTPER / 256, 256>>>();
    wperm_kernel<<<(16 * NMBLK * A_WORDS + 255) / 256, 256>>>(W);
    xpermute_kernel<<<(BATCH * DIM * SEQL / 2 + 255) / 256, 256>>>(x);

    nyq_kernel<<<NCOL / 256, 256>>>(x, W, bias);

    gemm1_mma<<<dim3(NMBLK, NCOL / BN), NTHR, SMEM_BYTES>>>(bias);

    ifft_ola_kernel<<<BATCH * (SEQL / HOPB), 256>>>(out);
}

// round 13
// speedup vs baseline: 6.8574x; 1.2017x over previous
#include <cuda_runtime.h>
#include <cuda_fp16.h>
#include <cstdint>
#include <math.h>

// Problem constants
#define BATCH   16
#define DIM     512
#define SEQL    4096
#define NFFT    1024
#define HOP     256
#define FBINS   513          // NFFT/2 + 1
#define NCOL    65536        // BATCH * SEQL
#define OUTPER  1048576      // SEQL * HOP
#define PAD     384          // (NFFT - HOP)/2
#define TWO_PI  6.283185307179586476925286766559f

// spec_T K layout: [Re: 0..512][pad][Im: 544..1056][pad]
#define KR      544
#define KTOT    1088

// GEMM1 covers bins 0..511 (8 mblocks); bin 512 handled by nyq_kernel.
#define NMBLK   8

// GEMM1 tiling: block 128x256, 512 threads, warp tile 64x32 (2x8 grid), fp16 mma
#define BM 128
#define BN 256
#define BK 32
#define NTHR 512
#define A_HALVES 4096            // per-stage A: 2 k16-groups x 8 mtiles x 32 lanes x 8
#define B_HALVES 8192            // per-stage B: 2 k16-groups x 32 ltiles x 32 lanes x 4
#define A_BYTES  (A_HALVES * 2)  // 8192
#define B_BYTES  (B_HALVES * 2)  // 16384
#define STAGE_BYTES (A_BYTES + B_BYTES)   // 24576
#define SMEM_BYTES 69632          // max(2*STAGE_BYTES=49152, Tt=128*136*4=69632)

// Fused iFFT+OLA: hops per block
#define HOPB 32

// ---------------------------------------------------------------------------
// Scratch (static device globals)
// ---------------------------------------------------------------------------
__device__ float  g_specT[(size_t)NCOL * KTOT];       // spec m-major [m][k], fp32
__device__ __half g_xB[(size_t)BATCH * DIM * SEQL];   // x, fragment-major fp16
__device__ __half g_Wp[(size_t)16 * NMBLK * A_HALVES];// W, fragment-major fp16
__device__ float2 g_tw[1024];                         // exp(+2*pi*i*a/1024)
__device__ float  g_winS[NFFT];                       // hann[n] / 1024
__device__ float  g_invenv[OUTPER];                   // 1 / window-square envelope

__device__ __forceinline__ void mma_f16(float c[4], const uint32_t a[4], const uint32_t b[2]) {
    asm volatile(
        "mma.sync.aligned.m16n8k16.row.col.f32.f16.f16.f32 "
        "{%0,%1,%2,%3}, {%4,%5,%6,%7}, {%8,%9}, {%0,%1,%2,%3};\n"
        : "+f"(c[0]), "+f"(c[1]), "+f"(c[2]), "+f"(c[3])
        : "r"(a[0]), "r"(a[1]), "r"(a[2]), "r"(a[3]), "r"(b[0]), "r"(b[1]));
}

#define CP_ASYNC_CG(dst_u32, src_ptr) \
    asm volatile("cp.async.cg.shared.global [%0], [%1], 16;\n" \
                 :: "r"(dst_u32), "l"(src_ptr))
#define CP_COMMIT() asm volatile("cp.async.commit_group;\n")
#define CP_WAIT1()  asm volatile("cp.async.wait_group 1;\n")
#define CP_WAIT0()  asm volatile("cp.async.wait_group 0;\n")

// ---------------------------------------------------------------------------
// Prep kernels
// ---------------------------------------------------------------------------
__global__ void gen_tables_kernel() {
    int i = blockIdx.x * blockDim.x + threadIdx.x;
    if (i < 1024) {
        float s, c;
        sincosf(TWO_PI * (float)i * (1.0f / 1024.0f), &s, &c);
        g_tw[i] = make_float2(c, s);
        float w = 0.5f * (1.0f - c);      // hann[i]
        g_winS[i] = w * (1.0f / 1024.0f);
    }
}

// Precompute 1/env(t): env = sum over valid frames of hann^2 (batch-independent).
__global__ void gen_invenv_kernel() {
    int t = blockIdx.x * blockDim.x + threadIdx.x;
    if (t >= OUTPER) return;
    int g = t + PAD;
    int lmin = (g - (NFFT - 1) + (HOP - 1)) >> 8;
    if (lmin < 0) lmin = 0;
    int lmax = g >> 8;
    if (lmax > SEQL - 1) lmax = SEQL - 1;
    float env = 0.0f;
    const float inv = 1.0f / (float)NFFT;
    for (int l = lmin; l <= lmax; ++l) {
        int n = g - (l << 8);
        float w = 0.5f * (1.0f - cosf(TWO_PI * (float)n * inv));
        env += w * w;
    }
    g_invenv[t] = 1.0f / (env > 1e-11f ? env : 1.0f);
}

// W -> fragment-major fp16 g_Wp[kchunk][mblock][k16idx][mtile][lane][8].
// m16n8k16 A frag: q=0..7 -> (row lr + ((q&2)?8:0), col 2lc + (q&1) + ((q&4)?8:0))
__global__ void wperm_kernel(const float* __restrict__ W) {
    int i = blockIdx.x * blockDim.x + threadIdx.x;
    if (i >= 16 * NMBLK * A_HALVES) return;
    int q     = i & 7;
    int lane  = (i >> 3) & 31;
    int mtile = (i >> 8) & 7;
    int k16i  = (i >> 11) & 1;
    int rest  = i >> 12;
    int mblock = rest & 7;
    int kchunk = rest >> 3;
    int lr = lane >> 2, lc = lane & 3;
    int k  = kchunk * 32 + k16i * 16 + 2 * lc + (q & 1) + ((q & 4) ? 8 : 0);
    int mp = mblock * 128 + mtile * 16 + lr + ((q & 2) ? 8 : 0);
    int tile = mp >> 4, w = mp & 15;
    int bin = tile * 8 + (w & 7);                 // < 512 always (NMBLK=8)
    int o = (w < 8) ? bin : (FBINS + bin);
    g_Wp[i] = __float2half_rn(W[(size_t)o * DIM + k]);
}

// x -> fragment-major fp16 g_xB[b][kchunk][lblock][k16idx][ltile][lane][4].
// m16n8k16 B frag (col-major): q=0..3 -> (k = 2lc + (q&1) + ((q&2)?8:0), n = lr)
__global__ void xpermute_kernel(const float* __restrict__ x) {
    int j = blockIdx.x * blockDim.x + threadIdx.x;   // 4-half unit index
    if (j >= BATCH * DIM * SEQL / 4) return;
    int lane  = j & 31;
    int ltile = (j >> 5) & 31;
    int k16i  = (j >> 10) & 1;
    int lblock = (j >> 11) & 15;
    int kchunk = (j >> 15) & 15;
    int b = j >> 19;
    int lr = lane >> 2, lc = lane & 3;
    int l = lblock * 256 + ltile * 8 + lr;
    int kb = kchunk * 32 + k16i * 16 + 2 * lc;
    const float* xb = x + (size_t)b * DIM * SEQL + l;
    __half2 h01 = make_half2(__float2half_rn(xb[(size_t)kb * SEQL]),
                             __float2half_rn(xb[(size_t)(kb + 1) * SEQL]));
    __half2 h23 = make_half2(__float2half_rn(xb[(size_t)(kb + 8) * SEQL]),
                             __float2half_rn(xb[(size_t)(kb + 9) * SEQL]));
    uint2 u;
    u.x = *(uint32_t*)&h01;
    u.y = *(uint32_t*)&h23;
    ((uint2*)g_xB)[j] = u;
}

// Nyquist bin (512): plain fp32 dot products, fused spectrum.
__global__ __launch_bounds__(256)
void nyq_kernel(const float* __restrict__ x, const float* __restrict__ W,
                const float* __restrict__ bias) {
    __shared__ float wm[DIM], wp[DIM];
    int tid = threadIdx.x;
    for (int k = tid; k < DIM; k += 256) {
        wm[k] = W[(size_t)512 * DIM + k];
        wp[k] = W[(size_t)1025 * DIM + k];
    }
    __syncthreads();
    int n = blockIdx.x * 256 + tid;
    int b = n >> 12, l = n & (SEQL - 1);
    const float* xb = x + (size_t)b * DIM * SEQL + l;
    float am = 0.0f, ap = 0.0f;
#pragma unroll 8
    for (int k = 0; k < DIM; k++) {
        float xv = xb[(size_t)k * SEQL];
        am += wm[k] * xv;
        ap += wp[k] * xv;
    }
    float mag = fminf(__expf(am + bias[512]), 100.0f);
    float s, c;
    __sincosf(ap + bias[1025], &s, &c);
    g_specT[(size_t)n * KTOT + 512]      = mag * c;
    g_specT[(size_t)n * KTOT + KR + 512] = mag * s;
}

// ---------------------------------------------------------------------------
// GEMM1 (FP16 m16n8k16 mma, fp32 accum, cp.async double-buffered,
// fragment-major operands, fused spectrum epilogue): bins 0..511.
// ---------------------------------------------------------------------------
__global__ __launch_bounds__(NTHR, 1)
void gemm1_mma(const float* __restrict__ bias) {
    extern __shared__ float sm[];
    const uint32_t smem_u32 = (uint32_t)__cvta_generic_to_shared(sm);

    const int mblock = blockIdx.x;
    const int n0 = blockIdx.y * BN;
    const int bidx = n0 >> 12;
    const int lblock = (n0 & (SEQL - 1)) >> 8;

    const int tid = threadIdx.x;
    const int wid = tid >> 5, lane = tid & 31;
    const int wn = (wid >> 1) * 32;
    const int lr = lane >> 2, lc = lane & 3;

    float acc[4][4][4];
#pragma unroll
    for (int i = 0; i < 4; i++)
#pragma unroll
        for (int j = 0; j < 4; j++)
#pragma unroll
            for (int q = 0; q < 4; q++) acc[i][j][q] = 0.0f;

    const int T = DIM / BK;   // 16 kchunks

    auto load_stage = [&](int s) {
        const uint32_t a_base = smem_u32 + (s & 1) * STAGE_BYTES;
        const uint32_t b_base = a_base + A_BYTES;
        const __half* asrc = g_Wp + ((size_t)s * NMBLK + mblock) * A_HALVES;
        const __half* bsrc = g_xB + ((size_t)bidx * 16 * 16 + (size_t)s * 16 + lblock) * B_HALVES;
        CP_ASYNC_CG(a_base + tid * 16, asrc + tid * 8);          // 8KB
#pragma unroll
        for (int i = 0; i < 2; i++) {                            // 16KB
            int ch = tid + NTHR * i;
            CP_ASYNC_CG(b_base + ch * 16, bsrc + ch * 8);
        }
        CP_COMMIT();
    };

    const int a_off = (wid & 1) * 1024 + lane * 8;   // halves
    const int b_off = (wid >> 1) * 512 + lane * 4;   // halves

    load_stage(0);
    for (int s = 0; s < T; s++) {
        if (s + 1 < T) { load_stage(s + 1); CP_WAIT1(); } else { CP_WAIT0(); }
        __syncthreads();
        const __half* As = (const __half*)((const char*)sm + (s & 1) * STAGE_BYTES);
        const __half* Bs = As + A_HALVES;
#pragma unroll
        for (int k16i = 0; k16i < 2; k16i++) {
            const __half* Ak = As + k16i * 2048 + a_off;   // [mtile][lane][8]
            const __half* Bk = Bs + k16i * 4096 + b_off;   // [ltile][lane][4]
            uint32_t af[4][4], bf[4][2];
#pragma unroll
            for (int im = 0; im < 4; im++) {
                uint4 v = *(const uint4*)(Ak + im * 256);
                af[im][0] = v.x; af[im][1] = v.y; af[im][2] = v.z; af[im][3] = v.w;
            }
#pragma unroll
            for (int jn = 0; jn < 4; jn++) {
                uint2 v = *(const uint2*)(Bk + jn * 128);
                bf[jn][0] = v.x; bf[jn][1] = v.y;
            }
#pragma unroll
            for (int im = 0; im < 4; im++)
#pragma unroll
                for (int jn = 0; jn < 4; jn++)
                    mma_f16(acc[im][jn], af[im], bf[jn]);
        }
        __syncthreads();
    }

    // ---- Fused spectrum epilogue, transposed to spec_T[m][k] ----
    // D frag of m16n8k16 == D frag of m16n8k8: indexing unchanged.
    const int TS = 136;
    float* Tt = sm;                        // 128 x 136 floats
    const int bin0 = mblock * 64;

    for (int h = 0; h < 2; h++) {
        if ((wid >> 3) == h) {
            int cbase = wn & 127;
#pragma unroll
            for (int im = 0; im < 4; im++) {
                int bin_l = ((wid & 1) * 4 + im) * 8 + lr;   // 0..63
                int bin = bin0 + bin_l;
                float bmag = bias[bin];
                float bph  = bias[FBINS + bin];
#pragma unroll
                for (int jn = 0; jn < 4; jn++) {
                    int c_l = cbase + jn * 8 + 2 * lc;
                    float m0v = fminf(__expf(acc[im][jn][0] + bmag), 100.0f);
                    float m1v = fminf(__expf(acc[im][jn][1] + bmag), 100.0f);
                    float s0, c0, s1, c1;
                    __sincosf(acc[im][jn][2] + bph, &s0, &c0);
                    __sincosf(acc[im][jn][3] + bph, &s1, &c1);
                    Tt[c_l * TS + bin_l]            = m0v * c0;
                    Tt[(c_l + 1) * TS + bin_l]      = m1v * c1;
                    Tt[c_l * TS + 64 + bin_l]       = m0v * s0;
                    Tt[(c_l + 1) * TS + 64 + bin_l] = m1v * s1;
                }
            }
        }
        __syncthreads();
        for (int sidx = wid; sidx < 256; sidx += 16) {
            int c_l = sidx >> 1, part = sidx & 1;
            int m_glob = n0 + h * 128 + c_l;
            float* dst = g_specT + (size_t)m_glob * KTOT + (part ? (KR + bin0) : bin0);
            const float* src = Tt + c_l * TS + part * 64;
            dst[lane]      = src[lane];
            dst[lane + 32] = src[lane + 32];
        }
        __syncthreads();
    }
}

// ---------------------------------------------------------------------------
// Fused iFFT + window + overlap-add (radix-4 Stockham, 5-slot ring).
// ---------------------------------------------------------------------------
__device__ __forceinline__ float2 cmul(float2 x, float2 w) {
    return make_float2(x.x * w.x - x.y * w.y, x.x * w.y + x.y * w.x);
}

__global__ __launch_bounds__(256)
void ifft_ola_kernel(float* __restrict__ out) {
    __shared__ float2 bufA[1024];
    __shared__ float2 bufB[1024];
    __shared__ float ring[5][1024];
    const int blk = blockIdx.x;
    const int b = blk / (SEQL / HOPB);
    const int h0 = (blk % (SEQL / HOPB)) * HOPB;
    const int tid = threadIdx.x;

    for (int l = h0 - 2; l <= h0 + HOPB + 1; ++l) {
        const int slot = (l + 10) % 5;
        if (l >= 0 && l < SEQL) {
            const float* src = g_specT + ((size_t)b * SEQL + l) * KTOT;
#pragma unroll
            for (int h2 = 0; h2 < 2; h2++) {
                int j = tid + h2 * 256;               // 0..511
                float re = src[j];
                float im = src[KR + j];
                bufA[j] = make_float2(re, im);
                if (j > 0) bufA[1024 - j] = make_float2(re, -im);
            }
            if (tid == 0)
                bufA[512] = make_float2(src[512], src[KR + 512]);
            __syncthreads();

            float2* X = bufA;
            float2* Y = bufB;
#pragma unroll
            for (int st = 0; st < 5; st++) {
                const int s = 1 << (2 * st);
                const int i = tid;
                float2 a = X[i];
                float2 bb = X[i + 256];
                float2 c = X[i + 512];
                float2 d = X[i + 768];
                float2 t0 = make_float2(a.x + c.x, a.y + c.y);
                float2 t1 = make_float2(a.x - c.x, a.y - c.y);
                float2 t2 = make_float2(bb.x + d.x, bb.y + d.y);
                float2 t3 = make_float2(-(bb.y - d.y), bb.x - d.x);   // +i*(b-d)
                int ps = i & ~(s - 1);
                int o  = (i & (s - 1)) + ((i >> (2 * st)) << (2 * st + 2));
                float2 F0 = make_float2(t0.x + t2.x, t0.y + t2.y);
                float2 F1 = make_float2(t1.x + t3.x, t1.y + t3.y);
                float2 F2 = make_float2(t0.x - t2.x, t0.y - t2.y);
                float2 F3 = make_float2(t1.x - t3.x, t1.y - t3.y);
                Y[o]         = F0;
                Y[o + s]     = cmul(F1, g_tw[ps]);
                Y[o + 2 * s] = cmul(F2, g_tw[2 * ps]);
                Y[o + 3 * s] = cmul(F3, g_tw[3 * ps]);
                __syncthreads();
                float2* t = X; X = Y; Y = t;
            }
#pragma unroll
            for (int h2 = 0; h2 < 4; h2++) {
                int n = tid + h2 * 256;
                ring[slot][n] = X[n].x * g_winS[n];
            }
        } else {
#pragma unroll
            for (int h2 = 0; h2 < 4; h2++)
                ring[slot][tid + h2 * 256] = 0.0f;
        }
        __syncthreads();

        const int h = l - 2;                 // hop emittable now
        if (h >= h0 && h < h0 + HOPB) {
            int t = h * HOP + tid;
            float acc = ring[(h - 1 + 10) % 5][640 + tid]
                      + ring[(h     + 10) % 5][384 + tid]
                      + ring[(h + 1 + 10) % 5][128 + tid];
            if (tid < 128)
                acc += ring[(h - 2 + 10) % 5][896 + tid];
            else
                acc += ring[(h + 2 + 10) % 5][tid - 128];
            out[(size_t)b * OUTPER + t] = acc * g_invenv[t];
        }
        __syncthreads();
    }
}

// ---------------------------------------------------------------------------
// Launch
// ---------------------------------------------------------------------------
extern "C" void kernel_launch(void* const* d_in, const int* in_sizes, int n_in,
                              void* d_out, int out_size) {
    const float* x    = (const float*)d_in[0];   // (16, 512, 4096)
    const float* W    = (const float*)d_in[1];   // (1026, 512)
    const float* bias = (const float*)d_in[2];   // (1026,)
    float* out = (float*)d_out;                  // (16, 1048576)

    cudaFuncSetAttribute(gemm1_mma, cudaFuncAttributeMaxDynamicSharedMemorySize, SMEM_BYTES);

    gen_tables_kernel<<<4, 256>>>();
    gen_invenv_kernel<<<OUTPER / 256, 256>>>();
    wperm_kernel<<<(16 * NMBLK * A_HALVES + 255) / 256, 256>>>(W);
    xpermute_kernel<<<(BATCH * DIM * SEQL / 4 + 255) / 256, 256>>>(x);

    nyq_kernel<<<NCOL / 256, 256>>>(x, W, bias);

    gemm1_mma<<<dim3(NMBLK, NCOL / BN), NTHR, SMEM_BYTES>>>(bias);

    ifft_ola_kernel<<<BATCH * (SEQL / HOPB), 256>>>(out);
}